// round 1
// baseline (speedup 1.0000x reference)
#include <cuda_runtime.h>

#define D_MODEL 1024
#define NHEAD 16
#define D_HEAD 64
#define D_FF 4096
#define BATCH 2
#define SEQ 2048
#define NTOK (BATCH*SEQ)   /* 4096 tokens */
#define LN_EPS 1e-5f

/* ------------------------------------------------------------------ */
/* Scratch (static __device__ arrays; no runtime allocation)           */
/* ------------------------------------------------------------------ */
__device__ float g_q   [(size_t)NTOK * D_MODEL];
__device__ float g_k   [(size_t)NTOK * D_MODEL];
__device__ float g_v   [(size_t)NTOK * D_MODEL];
__device__ float g_att [(size_t)NTOK * D_MODEL];
__device__ float g_proj[(size_t)NTOK * D_MODEL];
__device__ float g_h   [(size_t)NTOK * D_MODEL];
__device__ float g_ffn [(size_t)NTOK * D_FF];
__device__ float g_f2  [(size_t)NTOK * D_MODEL];

/* ------------------------------------------------------------------ */
/* GEMM:  C[M,N] = A[M,K] @ B[N,K]^T + bias[N]   (optionally ReLU)     */
/* A row-major MxK, B row-major NxK (both K-contiguous -> NT gemm)     */
/* BM=BN=128, BK=16, 256 threads, 8x8 per thread                      */
/* ------------------------------------------------------------------ */
template<bool RELU>
__global__ __launch_bounds__(256)
void gemm_nt_bias(const float* __restrict__ A,
                  const float* __restrict__ B,
                  const float* __restrict__ bias,
                  float* __restrict__ C,
                  int M, int N, int K)
{
    const int BM = 128, BN = 128, BK = 16;
    __shared__ float As[BK][BM];
    __shared__ float Bs[BK][BN];

    const int bm0 = blockIdx.y * BM;
    const int bn0 = blockIdx.x * BN;
    const int t  = threadIdx.x;
    const int tx = t & 15;      /* 0..15 -> column group */
    const int ty = t >> 4;      /* 0..15 -> row group    */

    float acc[8][8];
#pragma unroll
    for (int i = 0; i < 8; i++)
#pragma unroll
        for (int j = 0; j < 8; j++) acc[i][j] = 0.f;

    for (int k0 = 0; k0 < K; k0 += BK) {
#pragma unroll
        for (int it = 0; it < 2; it++) {
            int idx = t + it * 256;          /* 0..511 float4 slots */
            int r   = idx >> 2;              /* 0..127 tile row     */
            int c4  = idx & 3;               /* 0..3 float4 in row  */
            float4 va = *(const float4*)&A[(size_t)(bm0 + r) * K + k0 + c4 * 4];
            As[c4*4+0][r] = va.x; As[c4*4+1][r] = va.y;
            As[c4*4+2][r] = va.z; As[c4*4+3][r] = va.w;
            float4 vb = *(const float4*)&B[(size_t)(bn0 + r) * K + k0 + c4 * 4];
            Bs[c4*4+0][r] = vb.x; Bs[c4*4+1][r] = vb.y;
            Bs[c4*4+2][r] = vb.z; Bs[c4*4+3][r] = vb.w;
        }
        __syncthreads();

#pragma unroll
        for (int k = 0; k < BK; k++) {
            float a[8], b[8];
            *(float4*)&a[0] = *(const float4*)&As[k][ty * 8];
            *(float4*)&a[4] = *(const float4*)&As[k][ty * 8 + 4];
            *(float4*)&b[0] = *(const float4*)&Bs[k][tx * 8];
            *(float4*)&b[4] = *(const float4*)&Bs[k][tx * 8 + 4];
#pragma unroll
            for (int i = 0; i < 8; i++)
#pragma unroll
                for (int j = 0; j < 8; j++)
                    acc[i][j] = fmaf(a[i], b[j], acc[i][j]);
        }
        __syncthreads();
    }

#pragma unroll
    for (int i = 0; i < 8; i++) {
        int row = bm0 + ty * 8 + i;
#pragma unroll
        for (int j = 0; j < 8; j += 4) {
            int col = bn0 + tx * 8 + j;
            float4 o;
            o.x = acc[i][j + 0] + bias[col + 0];
            o.y = acc[i][j + 1] + bias[col + 1];
            o.z = acc[i][j + 2] + bias[col + 2];
            o.w = acc[i][j + 3] + bias[col + 3];
            if (RELU) {
                o.x = fmaxf(o.x, 0.f); o.y = fmaxf(o.y, 0.f);
                o.z = fmaxf(o.z, 0.f); o.w = fmaxf(o.w, 0.f);
            }
            *(float4*)&C[(size_t)row * N + col] = o;
        }
    }
}

/* ------------------------------------------------------------------ */
/* Flash-style attention.  Layout: Q/K/V are [NTOK, D_MODEL] with head */
/* h occupying columns [h*64, h*64+64).  Output written in the same    */
/* (concat) layout.  One CTA = 32 query rows of one (b,h).             */
/* 8 warps, each warp owns 4 query rows; lane j owns key j of the      */
/* 32-key tile; lane also owns output dims d = 2*lane, 2*lane+1.       */
/* ------------------------------------------------------------------ */
__global__ __launch_bounds__(256)
void attn_kernel(const float* __restrict__ Q,
                 const float* __restrict__ K,
                 const float* __restrict__ V,
                 float* __restrict__ O)
{
    const int KSTR = 68;                 /* padded K smem stride (bank-safe) */
    __shared__ float Qs[32][64];
    __shared__ float Ks[32][KSTR];
    __shared__ float Vs[32][64];
    __shared__ float Ps[8][4][32];

    const int b = blockIdx.z, h = blockIdx.y;
    const int q0 = blockIdx.x * 32;
    const int t = threadIdx.x, warp = t >> 5, lane = t & 31;
    const size_t base = ((size_t)b * SEQ) * D_MODEL + (size_t)h * D_HEAD;

    /* load Q block: 32 x 64 floats = 512 float4 */
    for (int idx = t; idx < 512; idx += 256) {
        int r = idx >> 4, c = idx & 15;
        *(float4*)&Qs[r][c * 4] =
            *(const float4*)&Q[base + (size_t)(q0 + r) * D_MODEL + c * 4];
    }

    float o[4][2];
    float m[4], l[4];
#pragma unroll
    for (int r = 0; r < 4; r++) { o[r][0] = o[r][1] = 0.f; m[r] = -1e30f; l[r] = 0.f; }
    const float scale = 0.125f;          /* 1/sqrt(64) */

    for (int k0 = 0; k0 < SEQ; k0 += 32) {
        __syncthreads();                 /* protect Ks/Vs (and Qs on iter 0) */
        for (int idx = t; idx < 512; idx += 256) {
            int r = idx >> 4, c = idx & 15;
            *(float4*)&Ks[r][c * 4] =
                *(const float4*)&K[base + (size_t)(k0 + r) * D_MODEL + c * 4];
            *(float4*)&Vs[r][c * 4] =
                *(const float4*)&V[base + (size_t)(k0 + r) * D_MODEL + c * 4];
        }
        __syncthreads();

        /* scores: lane computes key=lane against warp's 4 rows */
        float s[4] = {0.f, 0.f, 0.f, 0.f};
#pragma unroll
        for (int c = 0; c < 16; c++) {
            float4 kv = *(const float4*)&Ks[lane][c * 4];
#pragma unroll
            for (int r = 0; r < 4; r++) {
                float4 qv = *(const float4*)&Qs[warp * 4 + r][c * 4];
                s[r] = fmaf(qv.x, kv.x, s[r]);
                s[r] = fmaf(qv.y, kv.y, s[r]);
                s[r] = fmaf(qv.z, kv.z, s[r]);
                s[r] = fmaf(qv.w, kv.w, s[r]);
            }
        }

        /* online softmax update */
#pragma unroll
        for (int r = 0; r < 4; r++) {
            float sc = s[r] * scale;
            float mx = sc;
#pragma unroll
            for (int off = 16; off > 0; off >>= 1)
                mx = fmaxf(mx, __shfl_xor_sync(0xffffffffu, mx, off));
            float mnew  = fmaxf(m[r], mx);
            float p     = __expf(sc - mnew);
            float alpha = __expf(m[r] - mnew);
            float psum  = p;
#pragma unroll
            for (int off = 16; off > 0; off >>= 1)
                psum += __shfl_xor_sync(0xffffffffu, psum, off);
            l[r] = l[r] * alpha + psum;
            m[r] = mnew;
            o[r][0] *= alpha;
            o[r][1] *= alpha;
            Ps[warp][r][lane] = p;
        }
        __syncwarp();

        /* accumulate P @ V : lane owns d = 2*lane, 2*lane+1 */
#pragma unroll 8
        for (int j = 0; j < 32; j++) {
            float2 vv = *(const float2*)&Vs[j][lane * 2];
#pragma unroll
            for (int r = 0; r < 4; r++) {
                float p = Ps[warp][r][j];
                o[r][0] = fmaf(p, vv.x, o[r][0]);
                o[r][1] = fmaf(p, vv.y, o[r][1]);
            }
        }
    }

#pragma unroll
    for (int r = 0; r < 4; r++) {
        float inv = 1.f / l[r];
        int row = q0 + warp * 4 + r;
        float2 ov;
        ov.x = o[r][0] * inv;
        ov.y = o[r][1] * inv;
        *(float2*)&O[base + (size_t)row * D_MODEL + lane * 2] = ov;
    }
}

/* ------------------------------------------------------------------ */
/* Fused residual add + LayerNorm: out_row = LN(a_row + b_row)         */
/* One CTA (256 threads) per 1024-wide row; each thread owns 4 elems.  */
/* ------------------------------------------------------------------ */
__global__ __launch_bounds__(256)
void add_ln_kernel(const float* __restrict__ A,
                   const float* __restrict__ B,
                   const float* __restrict__ gamma,
                   const float* __restrict__ beta,
                   float* __restrict__ out)
{
    const int row = blockIdx.x;
    const int t = threadIdx.x;
    const size_t roff = (size_t)row * D_MODEL;

    float4 va = *(const float4*)&A[roff + t * 4];
    float4 vb = *(const float4*)&B[roff + t * 4];
    float v0 = va.x + vb.x, v1 = va.y + vb.y, v2 = va.z + vb.z, v3 = va.w + vb.w;

    float s  = v0 + v1 + v2 + v3;
    float s2 = v0 * v0 + v1 * v1 + v2 * v2 + v3 * v3;

    __shared__ float red[2][8];
#pragma unroll
    for (int off = 16; off > 0; off >>= 1) {
        s  += __shfl_xor_sync(0xffffffffu, s,  off);
        s2 += __shfl_xor_sync(0xffffffffu, s2, off);
    }
    int warp = t >> 5, lane = t & 31;
    if (lane == 0) { red[0][warp] = s; red[1][warp] = s2; }
    __syncthreads();
    if (warp == 0) {
        s  = red[0][lane & 7];
        s2 = red[1][lane & 7];
#pragma unroll
        for (int off = 4; off > 0; off >>= 1) {
            s  += __shfl_xor_sync(0xffffffffu, s,  off);
            s2 += __shfl_xor_sync(0xffffffffu, s2, off);
        }
        if (lane == 0) { red[0][0] = s; red[1][0] = s2; }
    }
    __syncthreads();
    s  = red[0][0];
    s2 = red[1][0];

    const float inv_n = 1.f / (float)D_MODEL;
    float mu   = s * inv_n;
    float var  = s2 * inv_n - mu * mu;
    float rstd = rsqrtf(var + LN_EPS);

    float4 g4  = *(const float4*)&gamma[t * 4];
    float4 be4 = *(const float4*)&beta[t * 4];
    float4 o;
    o.x = (v0 - mu) * rstd * g4.x + be4.x;
    o.y = (v1 - mu) * rstd * g4.y + be4.y;
    o.z = (v2 - mu) * rstd * g4.z + be4.z;
    o.w = (v3 - mu) * rstd * g4.w + be4.w;
    *(float4*)&out[roff + t * 4] = o;
}

/* ------------------------------------------------------------------ */
/* Launcher                                                            */
/* ------------------------------------------------------------------ */
extern "C" void kernel_launch(void* const* d_in, const int* in_sizes, int n_in,
                              void* d_out, int out_size)
{
    const float* x   = (const float*)d_in[0];
    const float* Wq  = (const float*)d_in[1];
    const float* bq  = (const float*)d_in[2];
    const float* Wk  = (const float*)d_in[3];
    const float* bk  = (const float*)d_in[4];
    const float* Wv  = (const float*)d_in[5];
    const float* bv  = (const float*)d_in[6];
    const float* Wo  = (const float*)d_in[7];
    const float* bo  = (const float*)d_in[8];
    const float* W1  = (const float*)d_in[9];
    const float* b1  = (const float*)d_in[10];
    const float* W2  = (const float*)d_in[11];
    const float* b2  = (const float*)d_in[12];
    const float* g1  = (const float*)d_in[13];
    const float* be1 = (const float*)d_in[14];
    const float* g2  = (const float*)d_in[15];
    const float* be2 = (const float*)d_in[16];
    float* out = (float*)d_out;

    float *q, *k, *v, *att, *proj, *h, *ffn, *f2;
    cudaGetSymbolAddress((void**)&q,    g_q);
    cudaGetSymbolAddress((void**)&k,    g_k);
    cudaGetSymbolAddress((void**)&v,    g_v);
    cudaGetSymbolAddress((void**)&att,  g_att);
    cudaGetSymbolAddress((void**)&proj, g_proj);
    cudaGetSymbolAddress((void**)&h,    g_h);
    cudaGetSymbolAddress((void**)&ffn,  g_ffn);
    cudaGetSymbolAddress((void**)&f2,   g_f2);

    dim3 blk(256);

    /* QKV projections: [4096,1024] @ [1024,1024]^T */
    dim3 g_sq(D_MODEL / 128, NTOK / 128);
    gemm_nt_bias<false><<<g_sq, blk>>>(x, Wq, bq, q, NTOK, D_MODEL, D_MODEL);
    gemm_nt_bias<false><<<g_sq, blk>>>(x, Wk, bk, k, NTOK, D_MODEL, D_MODEL);
    gemm_nt_bias<false><<<g_sq, blk>>>(x, Wv, bv, v, NTOK, D_MODEL, D_MODEL);

    /* attention -> att (concat layout) */
    dim3 g_at(SEQ / 32, NHEAD, BATCH);
    attn_kernel<<<g_at, blk>>>(q, k, v, att);

    /* output projection */
    gemm_nt_bias<false><<<g_sq, blk>>>(att, Wo, bo, proj, NTOK, D_MODEL, D_MODEL);

    /* h = LN(x + proj) */
    add_ln_kernel<<<NTOK, blk>>>(x, proj, g1, be1, h);

    /* FFN */
    dim3 g_f1(D_FF / 128, NTOK / 128);
    gemm_nt_bias<true ><<<g_f1, blk>>>(h,   W1, b1, ffn, NTOK, D_FF,    D_MODEL);
    gemm_nt_bias<false><<<g_sq, blk>>>(ffn, W2, b2, f2,  NTOK, D_MODEL, D_FF);

    /* out = LN(h + f2) */
    add_ln_kernel<<<NTOK, blk>>>(h, f2, g2, be2, out);
}

// round 6
// speedup vs baseline: 1.7116x; 1.7116x over previous
#include <cuda_runtime.h>
#include <cstdint>

#define D_MODEL 1024
#define NHEAD 16
#define D_HEAD 64
#define D_FF 4096
#define BATCH 2
#define SEQ 2048
#define NTOK (BATCH*SEQ)   /* 4096 tokens */
#define LN_EPS 1e-5f

/* ------------------------------------------------------------------ */
/* Scratch (static __device__ arrays; no runtime allocation)           */
/* ------------------------------------------------------------------ */
__device__ float g_q   [(size_t)NTOK * D_MODEL];
__device__ float g_k   [(size_t)NTOK * D_MODEL];
__device__ float g_v   [(size_t)NTOK * D_MODEL];
__device__ float g_att [(size_t)NTOK * D_MODEL];
__device__ float g_proj[(size_t)NTOK * D_MODEL];
__device__ float g_h   [(size_t)NTOK * D_MODEL];
__device__ float g_ffn [(size_t)NTOK * D_FF];
__device__ float g_f2  [(size_t)NTOK * D_MODEL];

/* ------------------------------------------------------------------ */
/* tf32 tensor-core GEMM:  C[M,N] = A[M,K] @ B[N,K]^T + bias (opt ReLU)*/
/* BM=BN=128, BK=16, 256 thr = 8 warps (2x4), warp tile 64x32          */
/* mma.sync.aligned.m16n8k8.row.col.f32.tf32.tf32.f32                  */
/* SMEM double-buffered, stride 20 (pad 4) -> conflict-free frag LDS   */
/* ------------------------------------------------------------------ */
__device__ __forceinline__ uint32_t f2tf32(float f) {
    uint32_t u;
    asm("cvt.rna.tf32.f32 %0, %1;" : "=r"(u) : "f"(f));
    return u;
}

template<bool RELU>
__global__ __launch_bounds__(256)
void gemm_tf32_nt(const float* __restrict__ A,
                  const float* __restrict__ B,
                  const float* __restrict__ bias,
                  float* __restrict__ C,
                  int M, int N, int K)
{
    __shared__ uint32_t As[2][128][20];
    __shared__ uint32_t Bs[2][128][20];

    const int bm0 = blockIdx.y * 128;
    const int bn0 = blockIdx.x * 128;
    const int t    = threadIdx.x;
    const int warp = t >> 5, lane = t & 31;
    const int wm = (warp >> 2) * 64;     /* warp row offset: 0 / 64     */
    const int wn = (warp & 3) * 32;      /* warp col offset: 0..96      */
    const int r  = lane >> 2;            /* 0..7  */
    const int c  = lane & 3;             /* 0..3  */

    float acc[4][4][4];
#pragma unroll
    for (int mt = 0; mt < 4; mt++)
#pragma unroll
        for (int nt = 0; nt < 4; nt++)
#pragma unroll
            for (int i = 0; i < 4; i++) acc[mt][nt][i] = 0.f;

    /* global-load slot mapping: 2 float4 per thread per operand tile */
    int g_row[2], g_c4[2];
#pragma unroll
    for (int i = 0; i < 2; i++) {
        int slot = t + i * 256;          /* 0..511 */
        g_row[i] = slot >> 2;            /* 0..127 */
        g_c4[i]  = slot & 3;             /* 0..3   */
    }

    float4 ra[2], rb[2];

    /* prologue: load k-block 0 */
#pragma unroll
    for (int i = 0; i < 2; i++) {
        ra[i] = *(const float4*)&A[(size_t)(bm0 + g_row[i]) * K + g_c4[i] * 4];
        rb[i] = *(const float4*)&B[(size_t)(bn0 + g_row[i]) * K + g_c4[i] * 4];
    }
#pragma unroll
    for (int i = 0; i < 2; i++) {
        uint32_t* pa = &As[0][g_row[i]][g_c4[i] * 4];
        pa[0] = f2tf32(ra[i].x); pa[1] = f2tf32(ra[i].y);
        pa[2] = f2tf32(ra[i].z); pa[3] = f2tf32(ra[i].w);
        uint32_t* pb = &Bs[0][g_row[i]][g_c4[i] * 4];
        pb[0] = f2tf32(rb[i].x); pb[1] = f2tf32(rb[i].y);
        pb[2] = f2tf32(rb[i].z); pb[3] = f2tf32(rb[i].w);
    }
    __syncthreads();

    const int niter = K >> 4;
    for (int it = 0; it < niter; ++it) {
        const int buf = it & 1;

        if (it + 1 < niter) {
            const int k0 = (it + 1) << 4;
#pragma unroll
            for (int i = 0; i < 2; i++) {
                ra[i] = *(const float4*)&A[(size_t)(bm0 + g_row[i]) * K + k0 + g_c4[i] * 4];
                rb[i] = *(const float4*)&B[(size_t)(bn0 + g_row[i]) * K + k0 + g_c4[i] * 4];
            }
        }

#pragma unroll
        for (int ks = 0; ks < 2; ++ks) {
            const int kk = ks * 8;
            uint32_t af[4][4], bf[4][2];
#pragma unroll
            for (int mt = 0; mt < 4; mt++) {
                const int m0 = wm + mt * 16;
                af[mt][0] = As[buf][m0 + r    ][kk + c    ];
                af[mt][1] = As[buf][m0 + r + 8][kk + c    ];
                af[mt][2] = As[buf][m0 + r    ][kk + c + 4];
                af[mt][3] = As[buf][m0 + r + 8][kk + c + 4];
            }
#pragma unroll
            for (int nt = 0; nt < 4; nt++) {
                const int n0 = wn + nt * 8;
                bf[nt][0] = Bs[buf][n0 + r][kk + c    ];
                bf[nt][1] = Bs[buf][n0 + r][kk + c + 4];
            }
#pragma unroll
            for (int mt = 0; mt < 4; mt++)
#pragma unroll
                for (int nt = 0; nt < 4; nt++) {
                    asm volatile(
                        "mma.sync.aligned.m16n8k8.row.col.f32.tf32.tf32.f32 "
                        "{%0,%1,%2,%3}, {%4,%5,%6,%7}, {%8,%9}, {%0,%1,%2,%3};\n"
                        : "+f"(acc[mt][nt][0]), "+f"(acc[mt][nt][1]),
                          "+f"(acc[mt][nt][2]), "+f"(acc[mt][nt][3])
                        : "r"(af[mt][0]), "r"(af[mt][1]),
                          "r"(af[mt][2]), "r"(af[mt][3]),
                          "r"(bf[nt][0]), "r"(bf[nt][1]));
                }
        }

        if (it + 1 < niter) {
            const int nb = buf ^ 1;
#pragma unroll
            for (int i = 0; i < 2; i++) {
                uint32_t* pa = &As[nb][g_row[i]][g_c4[i] * 4];
                pa[0] = f2tf32(ra[i].x); pa[1] = f2tf32(ra[i].y);
                pa[2] = f2tf32(ra[i].z); pa[3] = f2tf32(ra[i].w);
                uint32_t* pb = &Bs[nb][g_row[i]][g_c4[i] * 4];
                pb[0] = f2tf32(rb[i].x); pb[1] = f2tf32(rb[i].y);
                pb[2] = f2tf32(rb[i].z); pb[3] = f2tf32(rb[i].w);
            }
        }
        __syncthreads();
    }

    /* epilogue: c0/c1 at (row, 2c), c2/c3 at (row+8, 2c) */
#pragma unroll
    for (int mt = 0; mt < 4; mt++) {
        const int mrow = bm0 + wm + mt * 16 + r;
#pragma unroll
        for (int nt = 0; nt < 4; nt++) {
            const int col = bn0 + wn + nt * 8 + 2 * c;
            const float b0 = bias[col], b1 = bias[col + 1];
            float o0 = acc[mt][nt][0] + b0;
            float o1 = acc[mt][nt][1] + b1;
            float o2 = acc[mt][nt][2] + b0;
            float o3 = acc[mt][nt][3] + b1;
            if (RELU) {
                o0 = fmaxf(o0, 0.f); o1 = fmaxf(o1, 0.f);
                o2 = fmaxf(o2, 0.f); o3 = fmaxf(o3, 0.f);
            }
            float2 v01 = make_float2(o0, o1);
            float2 v23 = make_float2(o2, o3);
            *(float2*)&C[(size_t)mrow * N + col]       = v01;
            *(float2*)&C[(size_t)(mrow + 8) * N + col] = v23;
        }
    }
}

/* ------------------------------------------------------------------ */
/* Flash-style attention (unchanged from R1).                          */
/* ------------------------------------------------------------------ */
__global__ __launch_bounds__(256)
void attn_kernel(const float* __restrict__ Q,
                 const float* __restrict__ K,
                 const float* __restrict__ V,
                 float* __restrict__ O)
{
    const int KSTR = 68;
    __shared__ float Qs[32][64];
    __shared__ float Ks[32][KSTR];
    __shared__ float Vs[32][64];
    __shared__ float Ps[8][4][32];

    const int b = blockIdx.z, h = blockIdx.y;
    const int q0 = blockIdx.x * 32;
    const int t = threadIdx.x, warp = t >> 5, lane = t & 31;
    const size_t base = ((size_t)b * SEQ) * D_MODEL + (size_t)h * D_HEAD;

    for (int idx = t; idx < 512; idx += 256) {
        int r = idx >> 4, c = idx & 15;
        *(float4*)&Qs[r][c * 4] =
            *(const float4*)&Q[base + (size_t)(q0 + r) * D_MODEL + c * 4];
    }

    float o[4][2];
    float m[4], l[4];
#pragma unroll
    for (int r = 0; r < 4; r++) { o[r][0] = o[r][1] = 0.f; m[r] = -1e30f; l[r] = 0.f; }
    const float scale = 0.125f;

    for (int k0 = 0; k0 < SEQ; k0 += 32) {
        __syncthreads();
        for (int idx = t; idx < 512; idx += 256) {
            int r = idx >> 4, c = idx & 15;
            *(float4*)&Ks[r][c * 4] =
                *(const float4*)&K[base + (size_t)(k0 + r) * D_MODEL + c * 4];
            *(float4*)&Vs[r][c * 4] =
                *(const float4*)&V[base + (size_t)(k0 + r) * D_MODEL + c * 4];
        }
        __syncthreads();

        float s[4] = {0.f, 0.f, 0.f, 0.f};
#pragma unroll
        for (int c = 0; c < 16; c++) {
            float4 kv = *(const float4*)&Ks[lane][c * 4];
#pragma unroll
            for (int r = 0; r < 4; r++) {
                float4 qv = *(const float4*)&Qs[warp * 4 + r][c * 4];
                s[r] = fmaf(qv.x, kv.x, s[r]);
                s[r] = fmaf(qv.y, kv.y, s[r]);
                s[r] = fmaf(qv.z, kv.z, s[r]);
                s[r] = fmaf(qv.w, kv.w, s[r]);
            }
        }

#pragma unroll
        for (int r = 0; r < 4; r++) {
            float sc = s[r] * scale;
            float mx = sc;
#pragma unroll
            for (int off = 16; off > 0; off >>= 1)
                mx = fmaxf(mx, __shfl_xor_sync(0xffffffffu, mx, off));
            float mnew  = fmaxf(m[r], mx);
            float p     = __expf(sc - mnew);
            float alpha = __expf(m[r] - mnew);
            float psum  = p;
#pragma unroll
            for (int off = 16; off > 0; off >>= 1)
                psum += __shfl_xor_sync(0xffffffffu, psum, off);
            l[r] = l[r] * alpha + psum;
            m[r] = mnew;
            o[r][0] *= alpha;
            o[r][1] *= alpha;
            Ps[warp][r][lane] = p;
        }
        __syncwarp();

#pragma unroll 8
        for (int j = 0; j < 32; j++) {
            float2 vv = *(const float2*)&Vs[j][lane * 2];
#pragma unroll
            for (int r = 0; r < 4; r++) {
                float p = Ps[warp][r][j];
                o[r][0] = fmaf(p, vv.x, o[r][0]);
                o[r][1] = fmaf(p, vv.y, o[r][1]);
            }
        }
    }

#pragma unroll
    for (int r = 0; r < 4; r++) {
        float inv = 1.f / l[r];
        int row = q0 + warp * 4 + r;
        float2 ov;
        ov.x = o[r][0] * inv;
        ov.y = o[r][1] * inv;
        *(float2*)&O[base + (size_t)row * D_MODEL + lane * 2] = ov;
    }
}

/* ------------------------------------------------------------------ */
/* Fused residual add + LayerNorm (unchanged)                          */
/* ------------------------------------------------------------------ */
__global__ __launch_bounds__(256)
void add_ln_kernel(const float* __restrict__ A,
                   const float* __restrict__ B,
                   const float* __restrict__ gamma,
                   const float* __restrict__ beta,
                   float* __restrict__ out)
{
    const int row = blockIdx.x;
    const int t = threadIdx.x;
    const size_t roff = (size_t)row * D_MODEL;

    float4 va = *(const float4*)&A[roff + t * 4];
    float4 vb = *(const float4*)&B[roff + t * 4];
    float v0 = va.x + vb.x, v1 = va.y + vb.y, v2 = va.z + vb.z, v3 = va.w + vb.w;

    float s  = v0 + v1 + v2 + v3;
    float s2 = v0 * v0 + v1 * v1 + v2 * v2 + v3 * v3;

    __shared__ float red[2][8];
#pragma unroll
    for (int off = 16; off > 0; off >>= 1) {
        s  += __shfl_xor_sync(0xffffffffu, s,  off);
        s2 += __shfl_xor_sync(0xffffffffu, s2, off);
    }
    int warp = t >> 5, lane = t & 31;
    if (lane == 0) { red[0][warp] = s; red[1][warp] = s2; }
    __syncthreads();
    if (warp == 0) {
        s  = red[0][lane & 7];
        s2 = red[1][lane & 7];
#pragma unroll
        for (int off = 4; off > 0; off >>= 1) {
            s  += __shfl_xor_sync(0xffffffffu, s,  off);
            s2 += __shfl_xor_sync(0xffffffffu, s2, off);
        }
        if (lane == 0) { red[0][0] = s; red[1][0] = s2; }
    }
    __syncthreads();
    s  = red[0][0];
    s2 = red[1][0];

    const float inv_n = 1.f / (float)D_MODEL;
    float mu   = s * inv_n;
    float var  = s2 * inv_n - mu * mu;
    float rstd = rsqrtf(var + LN_EPS);

    float4 g4  = *(const float4*)&gamma[t * 4];
    float4 be4 = *(const float4*)&beta[t * 4];
    float4 o;
    o.x = (v0 - mu) * rstd * g4.x + be4.x;
    o.y = (v1 - mu) * rstd * g4.y + be4.y;
    o.z = (v2 - mu) * rstd * g4.z + be4.z;
    o.w = (v3 - mu) * rstd * g4.w + be4.w;
    *(float4*)&out[roff + t * 4] = o;
}

/* ------------------------------------------------------------------ */
/* Launcher                                                            */
/* ------------------------------------------------------------------ */
extern "C" void kernel_launch(void* const* d_in, const int* in_sizes, int n_in,
                              void* d_out, int out_size)
{
    const float* x   = (const float*)d_in[0];
    const float* Wq  = (const float*)d_in[1];
    const float* bq  = (const float*)d_in[2];
    const float* Wk  = (const float*)d_in[3];
    const float* bk  = (const float*)d_in[4];
    const float* Wv  = (const float*)d_in[5];
    const float* bv  = (const float*)d_in[6];
    const float* Wo  = (const float*)d_in[7];
    const float* bo  = (const float*)d_in[8];
    const float* W1  = (const float*)d_in[9];
    const float* b1  = (const float*)d_in[10];
    const float* W2  = (const float*)d_in[11];
    const float* b2  = (const float*)d_in[12];
    const float* g1  = (const float*)d_in[13];
    const float* be1 = (const float*)d_in[14];
    const float* g2  = (const float*)d_in[15];
    const float* be2 = (const float*)d_in[16];
    float* out = (float*)d_out;

    float *q, *k, *v, *att, *proj, *h, *ffn, *f2;
    cudaGetSymbolAddress((void**)&q,    g_q);
    cudaGetSymbolAddress((void**)&k,    g_k);
    cudaGetSymbolAddress((void**)&v,    g_v);
    cudaGetSymbolAddress((void**)&att,  g_att);
    cudaGetSymbolAddress((void**)&proj, g_proj);
    cudaGetSymbolAddress((void**)&h,    g_h);
    cudaGetSymbolAddress((void**)&ffn,  g_ffn);
    cudaGetSymbolAddress((void**)&f2,   g_f2);

    dim3 blk(256);

    /* QKV projections: [4096,1024] @ [1024,1024]^T */
    dim3 g_sq(D_MODEL / 128, NTOK / 128);
    gemm_tf32_nt<false><<<g_sq, blk>>>(x, Wq, bq, q, NTOK, D_MODEL, D_MODEL);
    gemm_tf32_nt<false><<<g_sq, blk>>>(x, Wk, bk, k, NTOK, D_MODEL, D_MODEL);
    gemm_tf32_nt<false><<<g_sq, blk>>>(x, Wv, bv, v, NTOK, D_MODEL, D_MODEL);

    /* attention -> att (concat layout) */
    dim3 g_at(SEQ / 32, NHEAD, BATCH);
    attn_kernel<<<g_at, blk>>>(q, k, v, att);

    /* output projection */
    gemm_tf32_nt<false><<<g_sq, blk>>>(att, Wo, bo, proj, NTOK, D_MODEL, D_MODEL);

    /* h = LN(x + proj) */
    add_ln_kernel<<<NTOK, blk>>>(x, proj, g1, be1, h);

    /* FFN */
    dim3 g_f1(D_FF / 128, NTOK / 128);
    gemm_tf32_nt<true ><<<g_f1, blk>>>(h,   W1, b1, ffn, NTOK, D_FF,    D_MODEL);
    gemm_tf32_nt<false><<<g_sq, blk>>>(ffn, W2, b2, f2,  NTOK, D_MODEL, D_FF);

    /* out = LN(h + f2) */
    add_ln_kernel<<<NTOK, blk>>>(h, f2, g2, be2, out);
}

// round 10
// speedup vs baseline: 2.9517x; 1.7245x over previous
#include <cuda_runtime.h>
#include <cstdint>

#define D_MODEL 1024
#define NHEAD 16
#define D_HEAD 64
#define D_FF 4096
#define BATCH 2
#define SEQ 2048
#define NTOK (BATCH*SEQ)   /* 4096 tokens */
#define LN_EPS 1e-5f

/* ------------------------------------------------------------------ */
/* Scratch (static __device__ arrays; no runtime allocation)           */
/* ------------------------------------------------------------------ */
__device__ float g_q   [(size_t)NTOK * D_MODEL];
__device__ float g_k   [(size_t)NTOK * D_MODEL];
__device__ float g_v   [(size_t)NTOK * D_MODEL];
__device__ float g_att [(size_t)NTOK * D_MODEL];
__device__ float g_proj[(size_t)NTOK * D_MODEL];
__device__ float g_h   [(size_t)NTOK * D_MODEL];
__device__ float g_ffn [(size_t)NTOK * D_FF];
__device__ float g_f2  [(size_t)NTOK * D_MODEL];

__device__ __forceinline__ uint32_t f2tf32(float f) {
    uint32_t u;
    asm("cvt.rna.tf32.f32 %0, %1;" : "=r"(u) : "f"(f));
    return u;
}

#define MMA_TF32(acc, a, b0, b1)                                        \
    asm volatile(                                                       \
        "mma.sync.aligned.m16n8k8.row.col.f32.tf32.tf32.f32 "           \
        "{%0,%1,%2,%3}, {%4,%5,%6,%7}, {%8,%9}, {%0,%1,%2,%3};\n"       \
        : "+f"(acc[0]), "+f"(acc[1]), "+f"(acc[2]), "+f"(acc[3])        \
        : "r"(a[0]), "r"(a[1]), "r"(a[2]), "r"(a[3]), "r"(b0), "r"(b1))

/* ------------------------------------------------------------------ */
/* tf32 tensor-core GEMM (unchanged from R2, validated)                */
/* ------------------------------------------------------------------ */
template<bool RELU>
__global__ __launch_bounds__(256)
void gemm_tf32_nt(const float* __restrict__ A,
                  const float* __restrict__ B,
                  const float* __restrict__ bias,
                  float* __restrict__ C,
                  int M, int N, int K)
{
    __shared__ uint32_t As[2][128][20];
    __shared__ uint32_t Bs[2][128][20];

    const int bm0 = blockIdx.y * 128;
    const int bn0 = blockIdx.x * 128;
    const int t    = threadIdx.x;
    const int warp = t >> 5, lane = t & 31;
    const int wm = (warp >> 2) * 64;
    const int wn = (warp & 3) * 32;
    const int r  = lane >> 2;
    const int c  = lane & 3;

    float acc[4][4][4];
#pragma unroll
    for (int mt = 0; mt < 4; mt++)
#pragma unroll
        for (int nt = 0; nt < 4; nt++)
#pragma unroll
            for (int i = 0; i < 4; i++) acc[mt][nt][i] = 0.f;

    int g_row[2], g_c4[2];
#pragma unroll
    for (int i = 0; i < 2; i++) {
        int slot = t + i * 256;
        g_row[i] = slot >> 2;
        g_c4[i]  = slot & 3;
    }

    float4 ra[2], rb[2];
#pragma unroll
    for (int i = 0; i < 2; i++) {
        ra[i] = *(const float4*)&A[(size_t)(bm0 + g_row[i]) * K + g_c4[i] * 4];
        rb[i] = *(const float4*)&B[(size_t)(bn0 + g_row[i]) * K + g_c4[i] * 4];
    }
#pragma unroll
    for (int i = 0; i < 2; i++) {
        uint32_t* pa = &As[0][g_row[i]][g_c4[i] * 4];
        pa[0] = f2tf32(ra[i].x); pa[1] = f2tf32(ra[i].y);
        pa[2] = f2tf32(ra[i].z); pa[3] = f2tf32(ra[i].w);
        uint32_t* pb = &Bs[0][g_row[i]][g_c4[i] * 4];
        pb[0] = f2tf32(rb[i].x); pb[1] = f2tf32(rb[i].y);
        pb[2] = f2tf32(rb[i].z); pb[3] = f2tf32(rb[i].w);
    }
    __syncthreads();

    const int niter = K >> 4;
    for (int it = 0; it < niter; ++it) {
        const int buf = it & 1;

        if (it + 1 < niter) {
            const int k0 = (it + 1) << 4;
#pragma unroll
            for (int i = 0; i < 2; i++) {
                ra[i] = *(const float4*)&A[(size_t)(bm0 + g_row[i]) * K + k0 + g_c4[i] * 4];
                rb[i] = *(const float4*)&B[(size_t)(bn0 + g_row[i]) * K + k0 + g_c4[i] * 4];
            }
        }

#pragma unroll
        for (int ks = 0; ks < 2; ++ks) {
            const int kk = ks * 8;
            uint32_t af[4][4], bf[4][2];
#pragma unroll
            for (int mt = 0; mt < 4; mt++) {
                const int m0 = wm + mt * 16;
                af[mt][0] = As[buf][m0 + r    ][kk + c    ];
                af[mt][1] = As[buf][m0 + r + 8][kk + c    ];
                af[mt][2] = As[buf][m0 + r    ][kk + c + 4];
                af[mt][3] = As[buf][m0 + r + 8][kk + c + 4];
            }
#pragma unroll
            for (int nt = 0; nt < 4; nt++) {
                const int n0 = wn + nt * 8;
                bf[nt][0] = Bs[buf][n0 + r][kk + c    ];
                bf[nt][1] = Bs[buf][n0 + r][kk + c + 4];
            }
#pragma unroll
            for (int mt = 0; mt < 4; mt++)
#pragma unroll
                for (int nt = 0; nt < 4; nt++)
                    MMA_TF32(acc[mt][nt], af[mt], bf[nt][0], bf[nt][1]);
        }

        if (it + 1 < niter) {
            const int nb = buf ^ 1;
#pragma unroll
            for (int i = 0; i < 2; i++) {
                uint32_t* pa = &As[nb][g_row[i]][g_c4[i] * 4];
                pa[0] = f2tf32(ra[i].x); pa[1] = f2tf32(ra[i].y);
                pa[2] = f2tf32(ra[i].z); pa[3] = f2tf32(ra[i].w);
                uint32_t* pb = &Bs[nb][g_row[i]][g_c4[i] * 4];
                pb[0] = f2tf32(rb[i].x); pb[1] = f2tf32(rb[i].y);
                pb[2] = f2tf32(rb[i].z); pb[3] = f2tf32(rb[i].w);
            }
        }
        __syncthreads();
    }

#pragma unroll
    for (int mt = 0; mt < 4; mt++) {
        const int mrow = bm0 + wm + mt * 16 + r;
#pragma unroll
        for (int nt = 0; nt < 4; nt++) {
            const int col = bn0 + wn + nt * 8 + 2 * c;
            const float b0 = bias[col], b1 = bias[col + 1];
            float o0 = acc[mt][nt][0] + b0;
            float o1 = acc[mt][nt][1] + b1;
            float o2 = acc[mt][nt][2] + b0;
            float o3 = acc[mt][nt][3] + b1;
            if (RELU) {
                o0 = fmaxf(o0, 0.f); o1 = fmaxf(o1, 0.f);
                o2 = fmaxf(o2, 0.f); o3 = fmaxf(o3, 0.f);
            }
            *(float2*)&C[(size_t)mrow * N + col]       = make_float2(o0, o1);
            *(float2*)&C[(size_t)(mrow + 8) * N + col] = make_float2(o2, o3);
        }
    }
}

/* ------------------------------------------------------------------ */
/* Tensor-core flash attention (tf32 MMA).                             */
/* CTA = 256 thr (8 warps), 128 q-rows; warp owns 16 rows.             */
/* KV tiles of 64 keys; K/V/P in SMEM (tf32, stride 68).               */
/* ------------------------------------------------------------------ */
#define AT_ST 68

__global__ __launch_bounds__(256)
void attn_tc_kernel(const float* __restrict__ Q,
                    const float* __restrict__ K,
                    const float* __restrict__ V,
                    float* __restrict__ O)
{
    extern __shared__ uint32_t sm[];
    uint32_t (*Ks)[AT_ST] = (uint32_t(*)[AT_ST])sm;                  /* [64][68]  */
    uint32_t (*Vs)[AT_ST] = (uint32_t(*)[AT_ST])(sm + 64 * AT_ST);   /* [64][68]  */
    uint32_t (*Ps)[AT_ST] = (uint32_t(*)[AT_ST])(sm + 128 * AT_ST);  /* [128][68] */

    const int b  = blockIdx.z, h = blockIdx.y;
    const int q0 = blockIdx.x * 128;
    const int t = threadIdx.x, w = t >> 5, lane = t & 31;
    const int r = lane >> 2, c = lane & 3;
    const size_t base = ((size_t)b * SEQ) * D_MODEL + (size_t)h * D_HEAD;

    /* ---- load Q tile [128 x 64] into Ps (tf32) ---- */
#pragma unroll
    for (int i = 0; i < 8; i++) {
        int slot = t + i * 256;           /* 0..2047 */
        int row = slot >> 4, c4 = slot & 15;
        float4 v4 = *(const float4*)&Q[base + (size_t)(q0 + row) * D_MODEL + c4 * 4];
        uint32_t* p = &Ps[row][c4 * 4];
        p[0] = f2tf32(v4.x); p[1] = f2tf32(v4.y);
        p[2] = f2tf32(v4.z); p[3] = f2tf32(v4.w);
    }
    __syncthreads();

    /* ---- hoist Q fragments to registers (warp rows w*16..w*16+15) ---- */
    uint32_t qf[8][4];
#pragma unroll
    for (int kt = 0; kt < 8; kt++) {
        int kk = kt * 8;
        qf[kt][0] = Ps[w * 16 + r    ][kk + c    ];
        qf[kt][1] = Ps[w * 16 + r + 8][kk + c    ];
        qf[kt][2] = Ps[w * 16 + r    ][kk + c + 4];
        qf[kt][3] = Ps[w * 16 + r + 8][kk + c + 4];
    }

    float oacc[8][4];
#pragma unroll
    for (int nt = 0; nt < 8; nt++)
#pragma unroll
        for (int i = 0; i < 4; i++) oacc[nt][i] = 0.f;
    float m0 = -1e30f, m1 = -1e30f, l0 = 0.f, l1 = 0.f;
    const float scale = 0.125f;           /* 1/sqrt(64) */

    for (int k0 = 0; k0 < SEQ; k0 += 64) {
        __syncthreads();                  /* previous tile fully consumed */
        /* ---- load K,V tiles [64 x 64] (tf32) ---- */
#pragma unroll
        for (int i = 0; i < 4; i++) {
            int slot = t + i * 256;       /* 0..1023 */
            int row = slot >> 4, c4 = slot & 15;
            float4 kv = *(const float4*)&K[base + (size_t)(k0 + row) * D_MODEL + c4 * 4];
            float4 vv = *(const float4*)&V[base + (size_t)(k0 + row) * D_MODEL + c4 * 4];
            uint32_t* pk = &Ks[row][c4 * 4];
            pk[0] = f2tf32(kv.x); pk[1] = f2tf32(kv.y);
            pk[2] = f2tf32(kv.z); pk[3] = f2tf32(kv.w);
            uint32_t* pv = &Vs[row][c4 * 4];
            pv[0] = f2tf32(vv.x); pv[1] = f2tf32(vv.y);
            pv[2] = f2tf32(vv.z); pv[3] = f2tf32(vv.w);
        }
        __syncthreads();

        /* ---- S = Q @ K^T : warp computes 16 x 64 ---- */
        float sacc[8][4];
#pragma unroll
        for (int nt = 0; nt < 8; nt++)
#pragma unroll
            for (int i = 0; i < 4; i++) sacc[nt][i] = 0.f;

#pragma unroll
        for (int kt = 0; kt < 8; kt++) {
            const int kk = kt * 8;
#pragma unroll
            for (int nt = 0; nt < 8; nt++) {
                uint32_t b0 = Ks[nt * 8 + r][kk + c    ];
                uint32_t b1 = Ks[nt * 8 + r][kk + c + 4];
                MMA_TF32(sacc[nt], qf[kt], b0, b1);
            }
        }

        /* ---- fragment online softmax (rows r and r+8) ---- */
        float mx0 = -1e30f, mx1 = -1e30f;
#pragma unroll
        for (int nt = 0; nt < 8; nt++) {
            mx0 = fmaxf(mx0, fmaxf(sacc[nt][0], sacc[nt][1]));
            mx1 = fmaxf(mx1, fmaxf(sacc[nt][2], sacc[nt][3]));
        }
        mx0 = fmaxf(mx0, __shfl_xor_sync(0xffffffffu, mx0, 1));
        mx0 = fmaxf(mx0, __shfl_xor_sync(0xffffffffu, mx0, 2));
        mx1 = fmaxf(mx1, __shfl_xor_sync(0xffffffffu, mx1, 1));
        mx1 = fmaxf(mx1, __shfl_xor_sync(0xffffffffu, mx1, 2));

        float mn0 = fmaxf(m0, mx0 * scale);
        float mn1 = fmaxf(m1, mx1 * scale);
        float a0 = __expf(m0 - mn0), a1 = __expf(m1 - mn1);
        m0 = mn0; m1 = mn1;

        float rs0 = 0.f, rs1 = 0.f;
#pragma unroll
        for (int nt = 0; nt < 8; nt++) {
            float p00 = __expf(sacc[nt][0] * scale - mn0);
            float p01 = __expf(sacc[nt][1] * scale - mn0);
            float p10 = __expf(sacc[nt][2] * scale - mn1);
            float p11 = __expf(sacc[nt][3] * scale - mn1);
            rs0 += p00 + p01; rs1 += p10 + p11;
            uint2 u0; u0.x = f2tf32(p00); u0.y = f2tf32(p01);
            uint2 u1; u1.x = f2tf32(p10); u1.y = f2tf32(p11);
            *(uint2*)&Ps[w * 16 + r    ][nt * 8 + 2 * c] = u0;
            *(uint2*)&Ps[w * 16 + r + 8][nt * 8 + 2 * c] = u1;
        }
        rs0 += __shfl_xor_sync(0xffffffffu, rs0, 1);
        rs0 += __shfl_xor_sync(0xffffffffu, rs0, 2);
        rs1 += __shfl_xor_sync(0xffffffffu, rs1, 1);
        rs1 += __shfl_xor_sync(0xffffffffu, rs1, 2);
        l0 = l0 * a0 + rs0;
        l1 = l1 * a1 + rs1;
#pragma unroll
        for (int nt = 0; nt < 8; nt++) {
            oacc[nt][0] *= a0; oacc[nt][1] *= a0;
            oacc[nt][2] *= a1; oacc[nt][3] *= a1;
        }
        __syncwarp();

        /* ---- O += P @ V : warp computes 16 x 64 ---- */
#pragma unroll
        for (int kt = 0; kt < 8; kt++) {
            const int kk = kt * 8;
            uint32_t af[4];
            af[0] = Ps[w * 16 + r    ][kk + c    ];
            af[1] = Ps[w * 16 + r + 8][kk + c    ];
            af[2] = Ps[w * 16 + r    ][kk + c + 4];
            af[3] = Ps[w * 16 + r + 8][kk + c + 4];
#pragma unroll
            for (int nt = 0; nt < 8; nt++) {
                uint32_t b0 = Vs[kk + c    ][nt * 8 + r];
                uint32_t b1 = Vs[kk + c + 4][nt * 8 + r];
                MMA_TF32(oacc[nt], af, b0, b1);
            }
        }
    }

    /* ---- epilogue: O /= l, write concat layout ---- */
    const float inv0 = 1.f / l0, inv1 = 1.f / l1;
    const int row0 = q0 + w * 16 + r;
#pragma unroll
    for (int nt = 0; nt < 8; nt++) {
        const int col = nt * 8 + 2 * c;
        *(float2*)&O[base + (size_t)row0 * D_MODEL + col] =
            make_float2(oacc[nt][0] * inv0, oacc[nt][1] * inv0);
        *(float2*)&O[base + (size_t)(row0 + 8) * D_MODEL + col] =
            make_float2(oacc[nt][2] * inv1, oacc[nt][3] * inv1);
    }
}

/* ------------------------------------------------------------------ */
/* Fused residual add + LayerNorm (unchanged)                          */
/* ------------------------------------------------------------------ */
__global__ __launch_bounds__(256)
void add_ln_kernel(const float* __restrict__ A,
                   const float* __restrict__ B,
                   const float* __restrict__ gamma,
                   const float* __restrict__ beta,
                   float* __restrict__ out)
{
    const int row = blockIdx.x;
    const int t = threadIdx.x;
    const size_t roff = (size_t)row * D_MODEL;

    float4 va = *(const float4*)&A[roff + t * 4];
    float4 vb = *(const float4*)&B[roff + t * 4];
    float v0 = va.x + vb.x, v1 = va.y + vb.y, v2 = va.z + vb.z, v3 = va.w + vb.w;

    float s  = v0 + v1 + v2 + v3;
    float s2 = v0 * v0 + v1 * v1 + v2 * v2 + v3 * v3;

    __shared__ float red[2][8];
#pragma unroll
    for (int off = 16; off > 0; off >>= 1) {
        s  += __shfl_xor_sync(0xffffffffu, s,  off);
        s2 += __shfl_xor_sync(0xffffffffu, s2, off);
    }
    int warp = t >> 5, lane = t & 31;
    if (lane == 0) { red[0][warp] = s; red[1][warp] = s2; }
    __syncthreads();
    if (warp == 0) {
        s  = red[0][lane & 7];
        s2 = red[1][lane & 7];
#pragma unroll
        for (int off = 4; off > 0; off >>= 1) {
            s  += __shfl_xor_sync(0xffffffffu, s,  off);
            s2 += __shfl_xor_sync(0xffffffffu, s2, off);
        }
        if (lane == 0) { red[0][0] = s; red[1][0] = s2; }
    }
    __syncthreads();
    s  = red[0][0];
    s2 = red[1][0];

    const float inv_n = 1.f / (float)D_MODEL;
    float mu   = s * inv_n;
    float var  = s2 * inv_n - mu * mu;
    float rstd = rsqrtf(var + LN_EPS);

    float4 g4  = *(const float4*)&gamma[t * 4];
    float4 be4 = *(const float4*)&beta[t * 4];
    float4 o;
    o.x = (v0 - mu) * rstd * g4.x + be4.x;
    o.y = (v1 - mu) * rstd * g4.y + be4.y;
    o.z = (v2 - mu) * rstd * g4.z + be4.z;
    o.w = (v3 - mu) * rstd * g4.w + be4.w;
    *(float4*)&out[roff + t * 4] = o;
}

/* ------------------------------------------------------------------ */
/* Launcher                                                            */
/* ------------------------------------------------------------------ */
extern "C" void kernel_launch(void* const* d_in, const int* in_sizes, int n_in,
                              void* d_out, int out_size)
{
    const float* x   = (const float*)d_in[0];
    const float* Wq  = (const float*)d_in[1];
    const float* bq  = (const float*)d_in[2];
    const float* Wk  = (const float*)d_in[3];
    const float* bk  = (const float*)d_in[4];
    const float* Wv  = (const float*)d_in[5];
    const float* bv  = (const float*)d_in[6];
    const float* Wo  = (const float*)d_in[7];
    const float* bo  = (const float*)d_in[8];
    const float* W1  = (const float*)d_in[9];
    const float* b1  = (const float*)d_in[10];
    const float* W2  = (const float*)d_in[11];
    const float* b2  = (const float*)d_in[12];
    const float* g1  = (const float*)d_in[13];
    const float* be1 = (const float*)d_in[14];
    const float* g2  = (const float*)d_in[15];
    const float* be2 = (const float*)d_in[16];
    float* out = (float*)d_out;

    float *q, *k, *v, *att, *proj, *h, *ffn, *f2;
    cudaGetSymbolAddress((void**)&q,    g_q);
    cudaGetSymbolAddress((void**)&k,    g_k);
    cudaGetSymbolAddress((void**)&v,    g_v);
    cudaGetSymbolAddress((void**)&att,  g_att);
    cudaGetSymbolAddress((void**)&proj, g_proj);
    cudaGetSymbolAddress((void**)&h,    g_h);
    cudaGetSymbolAddress((void**)&ffn,  g_ffn);
    cudaGetSymbolAddress((void**)&f2,   g_f2);

    dim3 blk(256);

    /* QKV projections: [4096,1024] @ [1024,1024]^T */
    dim3 g_sq(D_MODEL / 128, NTOK / 128);
    gemm_tf32_nt<false><<<g_sq, blk>>>(x, Wq, bq, q, NTOK, D_MODEL, D_MODEL);
    gemm_tf32_nt<false><<<g_sq, blk>>>(x, Wk, bk, k, NTOK, D_MODEL, D_MODEL);
    gemm_tf32_nt<false><<<g_sq, blk>>>(x, Wv, bv, v, NTOK, D_MODEL, D_MODEL);

    /* tensor-core flash attention -> att (concat layout) */
    static int smem_set = 0;
    const int at_smem = 256 * AT_ST * (int)sizeof(uint32_t);   /* 69632 B */
    if (!smem_set) {
        cudaFuncSetAttribute(attn_tc_kernel,
                             cudaFuncAttributeMaxDynamicSharedMemorySize, at_smem);
        smem_set = 1;
    }
    dim3 g_at(SEQ / 128, NHEAD, BATCH);
    attn_tc_kernel<<<g_at, blk, at_smem>>>(q, k, v, att);

    /* output projection */
    gemm_tf32_nt<false><<<g_sq, blk>>>(att, Wo, bo, proj, NTOK, D_MODEL, D_MODEL);

    /* h = LN(x + proj) */
    add_ln_kernel<<<NTOK, blk>>>(x, proj, g1, be1, h);

    /* FFN */
    dim3 g_f1(D_FF / 128, NTOK / 128);
    gemm_tf32_nt<true ><<<g_f1, blk>>>(h,   W1, b1, ffn, NTOK, D_FF,    D_MODEL);
    gemm_tf32_nt<false><<<g_sq, blk>>>(ffn, W2, b2, f2,  NTOK, D_MODEL, D_FF);

    /* out = LN(h + f2) */
    add_ln_kernel<<<NTOK, blk>>>(h, f2, g2, be2, out);
}

// round 11
// speedup vs baseline: 3.6121x; 1.2238x over previous
#include <cuda_runtime.h>
#include <cstdint>

#define D_MODEL 1024
#define NHEAD 16
#define D_HEAD 64
#define D_FF 4096
#define BATCH 2
#define SEQ 2048
#define NTOK (BATCH*SEQ)   /* 4096 tokens */
#define LN_EPS 1e-5f

/* ------------------------------------------------------------------ */
/* Scratch (static __device__ arrays; no runtime allocation)           */
/* ------------------------------------------------------------------ */
__device__ float g_q   [(size_t)NTOK * D_MODEL];
__device__ float g_k   [(size_t)NTOK * D_MODEL];
__device__ float g_v   [(size_t)NTOK * D_MODEL];
__device__ float g_att [(size_t)NTOK * D_MODEL];
__device__ float g_proj[(size_t)NTOK * D_MODEL];
__device__ float g_h   [(size_t)NTOK * D_MODEL];
__device__ float g_ffn [(size_t)NTOK * D_FF];
__device__ float g_f2  [(size_t)NTOK * D_MODEL];

/* tf32 MMA, fp32 bits fed directly (HW truncates to 19 bits) */
#define MMA_TF32(acc, a, b0, b1)                                        \
    asm volatile(                                                       \
        "mma.sync.aligned.m16n8k8.row.col.f32.tf32.tf32.f32 "           \
        "{%0,%1,%2,%3}, {%4,%5,%6,%7}, {%8,%9}, {%0,%1,%2,%3};\n"       \
        : "+f"(acc[0]), "+f"(acc[1]), "+f"(acc[2]), "+f"(acc[3])        \
        : "r"(a[0]), "r"(a[1]), "r"(a[2]), "r"(a[3]), "r"(b0), "r"(b1))

__device__ __forceinline__ void cpa16(void* s, const void* g) {
    uint32_t sa = (uint32_t)__cvta_generic_to_shared(s);
    asm volatile("cp.async.cg.shared.global [%0], [%1], 16;" :: "r"(sa), "l"(g));
}
#define CP_COMMIT() asm volatile("cp.async.commit_group;")
#define CP_WAIT0()  asm volatile("cp.async.wait_group 0;")
#define CP_WAIT1()  asm volatile("cp.async.wait_group 1;")

/* ------------------------------------------------------------------ */
/* tf32 GEMM body:  C[M,N] = A[M,K] @ B[N,K]^T + bias  (opt ReLU)      */
/* cp.async double-buffered, no conversions.                           */
/* ------------------------------------------------------------------ */
template<bool RELU>
__device__ __forceinline__
void gemm_body(const float* __restrict__ A,
               const float* __restrict__ B,
               const float* __restrict__ bias,
               float* __restrict__ C,
               int M, int N, int K,
               float (*As)[128][20], float (*Bs)[128][20])
{
    const int bm0 = blockIdx.y * 128;
    const int bn0 = blockIdx.x * 128;
    const int t    = threadIdx.x;
    const int warp = t >> 5, lane = t & 31;
    const int wm = (warp >> 2) * 64;
    const int wn = (warp & 3) * 32;
    const int r  = lane >> 2;
    const int c  = lane & 3;

    float acc[4][4][4];
#pragma unroll
    for (int mt = 0; mt < 4; mt++)
#pragma unroll
        for (int nt = 0; nt < 4; nt++)
#pragma unroll
            for (int i = 0; i < 4; i++) acc[mt][nt][i] = 0.f;

    int g_row[2], g_c4[2];
#pragma unroll
    for (int i = 0; i < 2; i++) {
        int slot = t + i * 256;
        g_row[i] = slot >> 2;
        g_c4[i]  = slot & 3;
    }

    const int niter = K >> 4;

    /* prologue: tile 0 -> buf 0 */
#pragma unroll
    for (int i = 0; i < 2; i++) {
        cpa16(&As[0][g_row[i]][g_c4[i] * 4],
              &A[(size_t)(bm0 + g_row[i]) * K + g_c4[i] * 4]);
        cpa16(&Bs[0][g_row[i]][g_c4[i] * 4],
              &B[(size_t)(bn0 + g_row[i]) * K + g_c4[i] * 4]);
    }
    CP_COMMIT();

    for (int it = 0; it < niter; ++it) {
        const int buf = it & 1;
        const bool has_next = (it + 1 < niter);

        if (has_next) {
            const int k0 = (it + 1) << 4;
            const int nb = buf ^ 1;
#pragma unroll
            for (int i = 0; i < 2; i++) {
                cpa16(&As[nb][g_row[i]][g_c4[i] * 4],
                      &A[(size_t)(bm0 + g_row[i]) * K + k0 + g_c4[i] * 4]);
                cpa16(&Bs[nb][g_row[i]][g_c4[i] * 4],
                      &B[(size_t)(bn0 + g_row[i]) * K + k0 + g_c4[i] * 4]);
            }
            CP_COMMIT();
            CP_WAIT1();
        } else {
            CP_WAIT0();
        }
        __syncthreads();

#pragma unroll
        for (int ks = 0; ks < 2; ++ks) {
            const int kk = ks * 8;
            uint32_t af[4][4], bf[4][2];
#pragma unroll
            for (int mt = 0; mt < 4; mt++) {
                const int m0 = wm + mt * 16;
                af[mt][0] = __float_as_uint(As[buf][m0 + r    ][kk + c    ]);
                af[mt][1] = __float_as_uint(As[buf][m0 + r + 8][kk + c    ]);
                af[mt][2] = __float_as_uint(As[buf][m0 + r    ][kk + c + 4]);
                af[mt][3] = __float_as_uint(As[buf][m0 + r + 8][kk + c + 4]);
            }
#pragma unroll
            for (int nt = 0; nt < 4; nt++) {
                const int n0 = wn + nt * 8;
                bf[nt][0] = __float_as_uint(Bs[buf][n0 + r][kk + c    ]);
                bf[nt][1] = __float_as_uint(Bs[buf][n0 + r][kk + c + 4]);
            }
#pragma unroll
            for (int mt = 0; mt < 4; mt++)
#pragma unroll
                for (int nt = 0; nt < 4; nt++)
                    MMA_TF32(acc[mt][nt], af[mt], bf[nt][0], bf[nt][1]);
        }
        __syncthreads();
    }

#pragma unroll
    for (int mt = 0; mt < 4; mt++) {
        const int mrow = bm0 + wm + mt * 16 + r;
#pragma unroll
        for (int nt = 0; nt < 4; nt++) {
            const int col = bn0 + wn + nt * 8 + 2 * c;
            const float b0 = bias[col], b1 = bias[col + 1];
            float o0 = acc[mt][nt][0] + b0;
            float o1 = acc[mt][nt][1] + b1;
            float o2 = acc[mt][nt][2] + b0;
            float o3 = acc[mt][nt][3] + b1;
            if (RELU) {
                o0 = fmaxf(o0, 0.f); o1 = fmaxf(o1, 0.f);
                o2 = fmaxf(o2, 0.f); o3 = fmaxf(o3, 0.f);
            }
            *(float2*)&C[(size_t)mrow * N + col]       = make_float2(o0, o1);
            *(float2*)&C[(size_t)(mrow + 8) * N + col] = make_float2(o2, o3);
        }
    }
}

template<bool RELU>
__global__ __launch_bounds__(256)
void gemm_tf32_nt(const float* __restrict__ A,
                  const float* __restrict__ B,
                  const float* __restrict__ bias,
                  float* __restrict__ C,
                  int M, int N, int K)
{
    __shared__ float As[2][128][20];
    __shared__ float Bs[2][128][20];
    gemm_body<RELU>(A, B, bias, C, M, N, K, As, Bs);
}

/* merged QKV: blockIdx.z selects weight/bias/output */
struct TriParams {
    const float* W[3];
    const float* b[3];
    float*       C[3];
};

__global__ __launch_bounds__(256)
void gemm_tf32_qkv(const float* __restrict__ A, TriParams p,
                   int M, int N, int K)
{
    __shared__ float As[2][128][20];
    __shared__ float Bs[2][128][20];
    const int z = blockIdx.z;
    gemm_body<false>(A, p.W[z], p.b[z], p.C[z], M, N, K, As, Bs);
}

/* ------------------------------------------------------------------ */
/* Tensor-core flash attention, cp.async double-buffered KV.           */
/* CTA = 256 thr (8 warps), 128 q-rows; warp owns 16 rows.             */
/* ------------------------------------------------------------------ */
#define AT_ST 68
#define AT_TILE_W (64 * AT_ST)            /* words per KV tile buffer */

__global__ __launch_bounds__(256)
void attn_tc_kernel(const float* __restrict__ Q,
                    const float* __restrict__ K,
                    const float* __restrict__ V,
                    float* __restrict__ O)
{
    extern __shared__ float sm[];
    float (*Ks)[64][AT_ST] = (float(*)[64][AT_ST])sm;                    /* [2][64][68] */
    float (*Vs)[64][AT_ST] = (float(*)[64][AT_ST])(sm + 2 * AT_TILE_W);  /* [2][64][68] */
    float (*Ps)[AT_ST]     = (float(*)[AT_ST])(sm + 4 * AT_TILE_W);      /* [128][68]   */

    const int b  = blockIdx.z, h = blockIdx.y;
    const int q0 = blockIdx.x * 128;
    const int t = threadIdx.x, w = t >> 5, lane = t & 31;
    const int r = lane >> 2, c = lane & 3;
    const size_t base = ((size_t)b * SEQ) * D_MODEL + (size_t)h * D_HEAD;

    /* prologue: issue KV tile 0 into buf 0 (overlaps with Q load) */
#pragma unroll
    for (int i = 0; i < 4; i++) {
        int slot = t + i * 256;
        int row = slot >> 4, c4 = slot & 15;
        cpa16(&Ks[0][row][c4 * 4], &K[base + (size_t)row * D_MODEL + c4 * 4]);
        cpa16(&Vs[0][row][c4 * 4], &V[base + (size_t)row * D_MODEL + c4 * 4]);
    }
    CP_COMMIT();

    /* load Q tile [128 x 64] into Ps (plain fp32) */
#pragma unroll
    for (int i = 0; i < 8; i++) {
        int slot = t + i * 256;
        int row = slot >> 4, c4 = slot & 15;
        *(float4*)&Ps[row][c4 * 4] =
            *(const float4*)&Q[base + (size_t)(q0 + row) * D_MODEL + c4 * 4];
    }
    __syncthreads();

    /* hoist Q fragments (fp32 bits) */
    uint32_t qf[8][4];
#pragma unroll
    for (int kt = 0; kt < 8; kt++) {
        int kk = kt * 8;
        qf[kt][0] = __float_as_uint(Ps[w * 16 + r    ][kk + c    ]);
        qf[kt][1] = __float_as_uint(Ps[w * 16 + r + 8][kk + c    ]);
        qf[kt][2] = __float_as_uint(Ps[w * 16 + r    ][kk + c + 4]);
        qf[kt][3] = __float_as_uint(Ps[w * 16 + r + 8][kk + c + 4]);
    }

    float oacc[8][4];
#pragma unroll
    for (int nt = 0; nt < 8; nt++)
#pragma unroll
        for (int i = 0; i < 4; i++) oacc[nt][i] = 0.f;
    float m0 = -1e30f, m1 = -1e30f, l0 = 0.f, l1 = 0.f;
    const float scale = 0.125f;           /* 1/sqrt(64) */

    const int ntiles = SEQ / 64;          /* 32 */
    for (int it = 0; it < ntiles; ++it) {
        const int buf = it & 1;
        const bool has_next = (it + 1 < ntiles);

        if (has_next) {
            const int k0n = (it + 1) * 64;
            const int nb = buf ^ 1;
#pragma unroll
            for (int i = 0; i < 4; i++) {
                int slot = t + i * 256;
                int row = slot >> 4, c4 = slot & 15;
                cpa16(&Ks[nb][row][c4 * 4],
                      &K[base + (size_t)(k0n + row) * D_MODEL + c4 * 4]);
                cpa16(&Vs[nb][row][c4 * 4],
                      &V[base + (size_t)(k0n + row) * D_MODEL + c4 * 4]);
            }
            CP_COMMIT();
            CP_WAIT1();
        } else {
            CP_WAIT0();
        }
        __syncthreads();

        /* ---- S = Q @ K^T : warp computes 16 x 64 ---- */
        float sacc[8][4];
#pragma unroll
        for (int nt = 0; nt < 8; nt++)
#pragma unroll
            for (int i = 0; i < 4; i++) sacc[nt][i] = 0.f;

#pragma unroll
        for (int kt = 0; kt < 8; kt++) {
            const int kk = kt * 8;
#pragma unroll
            for (int nt = 0; nt < 8; nt++) {
                uint32_t b0 = __float_as_uint(Ks[buf][nt * 8 + r][kk + c    ]);
                uint32_t b1 = __float_as_uint(Ks[buf][nt * 8 + r][kk + c + 4]);
                MMA_TF32(sacc[nt], qf[kt], b0, b1);
            }
        }

        /* ---- fragment online softmax (rows r and r+8) ---- */
        float mx0 = -1e30f, mx1 = -1e30f;
#pragma unroll
        for (int nt = 0; nt < 8; nt++) {
            mx0 = fmaxf(mx0, fmaxf(sacc[nt][0], sacc[nt][1]));
            mx1 = fmaxf(mx1, fmaxf(sacc[nt][2], sacc[nt][3]));
        }
        mx0 = fmaxf(mx0, __shfl_xor_sync(0xffffffffu, mx0, 1));
        mx0 = fmaxf(mx0, __shfl_xor_sync(0xffffffffu, mx0, 2));
        mx1 = fmaxf(mx1, __shfl_xor_sync(0xffffffffu, mx1, 1));
        mx1 = fmaxf(mx1, __shfl_xor_sync(0xffffffffu, mx1, 2));

        float mn0 = fmaxf(m0, mx0 * scale);
        float mn1 = fmaxf(m1, mx1 * scale);
        float a0 = __expf(m0 - mn0), a1 = __expf(m1 - mn1);
        m0 = mn0; m1 = mn1;

        float rs0 = 0.f, rs1 = 0.f;
#pragma unroll
        for (int nt = 0; nt < 8; nt++) {
            float p00 = __expf(sacc[nt][0] * scale - mn0);
            float p01 = __expf(sacc[nt][1] * scale - mn0);
            float p10 = __expf(sacc[nt][2] * scale - mn1);
            float p11 = __expf(sacc[nt][3] * scale - mn1);
            rs0 += p00 + p01; rs1 += p10 + p11;
            *(float2*)&Ps[w * 16 + r    ][nt * 8 + 2 * c] = make_float2(p00, p01);
            *(float2*)&Ps[w * 16 + r + 8][nt * 8 + 2 * c] = make_float2(p10, p11);
        }
        rs0 += __shfl_xor_sync(0xffffffffu, rs0, 1);
        rs0 += __shfl_xor_sync(0xffffffffu, rs0, 2);
        rs1 += __shfl_xor_sync(0xffffffffu, rs1, 1);
        rs1 += __shfl_xor_sync(0xffffffffu, rs1, 2);
        l0 = l0 * a0 + rs0;
        l1 = l1 * a1 + rs1;
#pragma unroll
        for (int nt = 0; nt < 8; nt++) {
            oacc[nt][0] *= a0; oacc[nt][1] *= a0;
            oacc[nt][2] *= a1; oacc[nt][3] *= a1;
        }
        __syncwarp();

        /* ---- O += P @ V : warp computes 16 x 64 ---- */
#pragma unroll
        for (int kt = 0; kt < 8; kt++) {
            const int kk = kt * 8;
            uint32_t af[4];
            af[0] = __float_as_uint(Ps[w * 16 + r    ][kk + c    ]);
            af[1] = __float_as_uint(Ps[w * 16 + r + 8][kk + c    ]);
            af[2] = __float_as_uint(Ps[w * 16 + r    ][kk + c + 4]);
            af[3] = __float_as_uint(Ps[w * 16 + r + 8][kk + c + 4]);
#pragma unroll
            for (int nt = 0; nt < 8; nt++) {
                uint32_t b0 = __float_as_uint(Vs[buf][kk + c    ][nt * 8 + r]);
                uint32_t b1 = __float_as_uint(Vs[buf][kk + c + 4][nt * 8 + r]);
                MMA_TF32(oacc[nt], af, b0, b1);
            }
        }
        __syncthreads();   /* all reads of buf done before its re-issue */
    }

    /* ---- epilogue ---- */
    const float inv0 = 1.f / l0, inv1 = 1.f / l1;
    const int row0 = q0 + w * 16 + r;
#pragma unroll
    for (int nt = 0; nt < 8; nt++) {
        const int col = nt * 8 + 2 * c;
        *(float2*)&O[base + (size_t)row0 * D_MODEL + col] =
            make_float2(oacc[nt][0] * inv0, oacc[nt][1] * inv0);
        *(float2*)&O[base + (size_t)(row0 + 8) * D_MODEL + col] =
            make_float2(oacc[nt][2] * inv1, oacc[nt][3] * inv1);
    }
}

/* ------------------------------------------------------------------ */
/* Fused residual add + LayerNorm (unchanged)                          */
/* ------------------------------------------------------------------ */
__global__ __launch_bounds__(256)
void add_ln_kernel(const float* __restrict__ A,
                   const float* __restrict__ B,
                   const float* __restrict__ gamma,
                   const float* __restrict__ beta,
                   float* __restrict__ out)
{
    const int row = blockIdx.x;
    const int t = threadIdx.x;
    const size_t roff = (size_t)row * D_MODEL;

    float4 va = *(const float4*)&A[roff + t * 4];
    float4 vb = *(const float4*)&B[roff + t * 4];
    float v0 = va.x + vb.x, v1 = va.y + vb.y, v2 = va.z + vb.z, v3 = va.w + vb.w;

    float s  = v0 + v1 + v2 + v3;
    float s2 = v0 * v0 + v1 * v1 + v2 * v2 + v3 * v3;

    __shared__ float red[2][8];
#pragma unroll
    for (int off = 16; off > 0; off >>= 1) {
        s  += __shfl_xor_sync(0xffffffffu, s,  off);
        s2 += __shfl_xor_sync(0xffffffffu, s2, off);
    }
    int warp = t >> 5, lane = t & 31;
    if (lane == 0) { red[0][warp] = s; red[1][warp] = s2; }
    __syncthreads();
    if (warp == 0) {
        s  = red[0][lane & 7];
        s2 = red[1][lane & 7];
#pragma unroll
        for (int off = 4; off > 0; off >>= 1) {
            s  += __shfl_xor_sync(0xffffffffu, s,  off);
            s2 += __shfl_xor_sync(0xffffffffu, s2, off);
        }
        if (lane == 0) { red[0][0] = s; red[1][0] = s2; }
    }
    __syncthreads();
    s  = red[0][0];
    s2 = red[1][0];

    const float inv_n = 1.f / (float)D_MODEL;
    float mu   = s * inv_n;
    float var  = s2 * inv_n - mu * mu;
    float rstd = rsqrtf(var + LN_EPS);

    float4 g4  = *(const float4*)&gamma[t * 4];
    float4 be4 = *(const float4*)&beta[t * 4];
    float4 o;
    o.x = (v0 - mu) * rstd * g4.x + be4.x;
    o.y = (v1 - mu) * rstd * g4.y + be4.y;
    o.z = (v2 - mu) * rstd * g4.z + be4.z;
    o.w = (v3 - mu) * rstd * g4.w + be4.w;
    *(float4*)&out[roff + t * 4] = o;
}

/* ------------------------------------------------------------------ */
/* Launcher                                                            */
/* ------------------------------------------------------------------ */
extern "C" void kernel_launch(void* const* d_in, const int* in_sizes, int n_in,
                              void* d_out, int out_size)
{
    const float* x   = (const float*)d_in[0];
    const float* Wq  = (const float*)d_in[1];
    const float* bq  = (const float*)d_in[2];
    const float* Wk  = (const float*)d_in[3];
    const float* bk  = (const float*)d_in[4];
    const float* Wv  = (const float*)d_in[5];
    const float* bv  = (const float*)d_in[6];
    const float* Wo  = (const float*)d_in[7];
    const float* bo  = (const float*)d_in[8];
    const float* W1  = (const float*)d_in[9];
    const float* b1  = (const float*)d_in[10];
    const float* W2  = (const float*)d_in[11];
    const float* b2  = (const float*)d_in[12];
    const float* g1  = (const float*)d_in[13];
    const float* be1 = (const float*)d_in[14];
    const float* g2  = (const float*)d_in[15];
    const float* be2 = (const float*)d_in[16];
    float* out = (float*)d_out;

    float *q, *k, *v, *att, *proj, *h, *ffn, *f2;
    cudaGetSymbolAddress((void**)&q,    g_q);
    cudaGetSymbolAddress((void**)&k,    g_k);
    cudaGetSymbolAddress((void**)&v,    g_v);
    cudaGetSymbolAddress((void**)&att,  g_att);
    cudaGetSymbolAddress((void**)&proj, g_proj);
    cudaGetSymbolAddress((void**)&h,    g_h);
    cudaGetSymbolAddress((void**)&ffn,  g_ffn);
    cudaGetSymbolAddress((void**)&f2,   g_f2);

    dim3 blk(256);

    /* merged QKV projections: z = 0/1/2 */
    TriParams tp;
    tp.W[0] = Wq; tp.W[1] = Wk; tp.W[2] = Wv;
    tp.b[0] = bq; tp.b[1] = bk; tp.b[2] = bv;
    tp.C[0] = q;  tp.C[1] = k;  tp.C[2] = v;
    dim3 g_qkv(D_MODEL / 128, NTOK / 128, 3);
    gemm_tf32_qkv<<<g_qkv, blk>>>(x, tp, NTOK, D_MODEL, D_MODEL);

    /* tensor-core flash attention -> att (concat layout) */
    static int smem_set = 0;
    const int at_smem = (4 * AT_TILE_W + 128 * AT_ST) * (int)sizeof(float); /* 104448 B */
    if (!smem_set) {
        cudaFuncSetAttribute(attn_tc_kernel,
                             cudaFuncAttributeMaxDynamicSharedMemorySize, at_smem);
        smem_set = 1;
    }
    dim3 g_at(SEQ / 128, NHEAD, BATCH);
    attn_tc_kernel<<<g_at, blk, at_smem>>>(q, k, v, att);

    /* output projection */
    dim3 g_sq(D_MODEL / 128, NTOK / 128);
    gemm_tf32_nt<false><<<g_sq, blk>>>(att, Wo, bo, proj, NTOK, D_MODEL, D_MODEL);

    /* h = LN(x + proj) */
    add_ln_kernel<<<NTOK, blk>>>(x, proj, g1, be1, h);

    /* FFN */
    dim3 g_f1(D_FF / 128, NTOK / 128);
    gemm_tf32_nt<true ><<<g_f1, blk>>>(h,   W1, b1, ffn, NTOK, D_FF,    D_MODEL);
    gemm_tf32_nt<false><<<g_sq, blk>>>(ffn, W2, b2, f2,  NTOK, D_MODEL, D_FF);

    /* out = LN(h + f2) */
    add_ln_kernel<<<NTOK, blk>>>(h, f2, g2, be2, out);
}

// round 12
// speedup vs baseline: 3.6519x; 1.0110x over previous
#include <cuda_runtime.h>
#include <cstdint>

#define D_MODEL 1024
#define NHEAD 16
#define D_HEAD 64
#define D_FF 4096
#define BATCH 2
#define SEQ 2048
#define NTOK (BATCH*SEQ)   /* 4096 tokens */
#define LN_EPS 1e-5f

/* ------------------------------------------------------------------ */
/* Scratch (static __device__ arrays; no runtime allocation)           */
/* ------------------------------------------------------------------ */
__device__ float g_q   [(size_t)NTOK * D_MODEL];
__device__ float g_k   [(size_t)NTOK * D_MODEL];
__device__ float g_v   [(size_t)NTOK * D_MODEL];
__device__ float g_att [(size_t)NTOK * D_MODEL];
__device__ float g_proj[(size_t)NTOK * D_MODEL];
__device__ float g_h   [(size_t)NTOK * D_MODEL];
__device__ float g_ffn [(size_t)NTOK * D_FF];
__device__ float g_f2  [(size_t)NTOK * D_MODEL];

/* tf32 MMA, fp32 bits fed directly (HW truncates to 19 bits) */
#define MMA_TF32(acc, a, b0, b1)                                        \
    asm volatile(                                                       \
        "mma.sync.aligned.m16n8k8.row.col.f32.tf32.tf32.f32 "           \
        "{%0,%1,%2,%3}, {%4,%5,%6,%7}, {%8,%9}, {%0,%1,%2,%3};\n"       \
        : "+f"(acc[0]), "+f"(acc[1]), "+f"(acc[2]), "+f"(acc[3])        \
        : "r"(a[0]), "r"(a[1]), "r"(a[2]), "r"(a[3]), "r"(b0), "r"(b1))

__device__ __forceinline__ void cpa16(void* s, const void* g) {
    uint32_t sa = (uint32_t)__cvta_generic_to_shared(s);
    asm volatile("cp.async.cg.shared.global [%0], [%1], 16;" :: "r"(sa), "l"(g));
}
#define CP_COMMIT() asm volatile("cp.async.commit_group;")
#define CP_WAIT0()  asm volatile("cp.async.wait_group 0;")
#define CP_WAIT1()  asm volatile("cp.async.wait_group 1;")

#define GSTAGES 3
/* per-stage tile: 128 rows x 20 (16 data + 4 pad) floats, A and B */
#define GTILE_W (128 * 20)
#define GEMM_SMEM_B (GSTAGES * 2 * GTILE_W * (int)sizeof(float))  /* 61440 */

/* ------------------------------------------------------------------ */
/* tf32 GEMM body:  C[M,N] = A[M,K] @ B[N,K]^T + bias  (opt ReLU)      */
/* 3-stage cp.async ring, 2 CTAs/SM.                                   */
/* ------------------------------------------------------------------ */
template<bool RELU>
__device__ __forceinline__
void gemm_body(const float* __restrict__ A,
               const float* __restrict__ B,
               const float* __restrict__ bias,
               float* __restrict__ C,
               int M, int N, int K,
               float (*As)[128][20], float (*Bs)[128][20])
{
    const int bm0 = blockIdx.y * 128;
    const int bn0 = blockIdx.x * 128;
    const int t    = threadIdx.x;
    const int warp = t >> 5, lane = t & 31;
    const int wm = (warp >> 2) * 64;
    const int wn = (warp & 3) * 32;
    const int r  = lane >> 2;
    const int c  = lane & 3;

    float acc[4][4][4];
#pragma unroll
    for (int mt = 0; mt < 4; mt++)
#pragma unroll
        for (int nt = 0; nt < 4; nt++)
#pragma unroll
            for (int i = 0; i < 4; i++) acc[mt][nt][i] = 0.f;

    int g_row[2], g_c4[2];
#pragma unroll
    for (int i = 0; i < 2; i++) {
        int slot = t + i * 256;
        g_row[i] = slot >> 2;
        g_c4[i]  = slot & 3;
    }

    const int niter = K >> 4;

    /* prologue: issue tiles 0 and 1 into stages 0,1 */
#pragma unroll
    for (int s = 0; s < GSTAGES - 1; ++s) {
        const int k0 = s << 4;
#pragma unroll
        for (int i = 0; i < 2; i++) {
            cpa16(&As[s][g_row[i]][g_c4[i] * 4],
                  &A[(size_t)(bm0 + g_row[i]) * K + k0 + g_c4[i] * 4]);
            cpa16(&Bs[s][g_row[i]][g_c4[i] * 4],
                  &B[(size_t)(bn0 + g_row[i]) * K + k0 + g_c4[i] * 4]);
        }
        CP_COMMIT();
    }

    int buf = 0;
    for (int it = 0; it < niter; ++it) {
        CP_WAIT1();                       /* tile `it` complete (<=1 pending) */
        __syncthreads();

#pragma unroll
        for (int ks = 0; ks < 2; ++ks) {
            const int kk = ks * 8;
            uint32_t af[4][4], bf[4][2];
#pragma unroll
            for (int mt = 0; mt < 4; mt++) {
                const int m0 = wm + mt * 16;
                af[mt][0] = __float_as_uint(As[buf][m0 + r    ][kk + c    ]);
                af[mt][1] = __float_as_uint(As[buf][m0 + r + 8][kk + c    ]);
                af[mt][2] = __float_as_uint(As[buf][m0 + r    ][kk + c + 4]);
                af[mt][3] = __float_as_uint(As[buf][m0 + r + 8][kk + c + 4]);
            }
#pragma unroll
            for (int nt = 0; nt < 4; nt++) {
                const int n0 = wn + nt * 8;
                bf[nt][0] = __float_as_uint(Bs[buf][n0 + r][kk + c    ]);
                bf[nt][1] = __float_as_uint(Bs[buf][n0 + r][kk + c + 4]);
            }
#pragma unroll
            for (int mt = 0; mt < 4; mt++)
#pragma unroll
                for (int nt = 0; nt < 4; nt++)
                    MMA_TF32(acc[mt][nt], af[mt], bf[nt][0], bf[nt][1]);
        }
        __syncthreads();                  /* buf fully consumed by all warps */

        const int nt_tile = it + GSTAGES - 1;
        if (nt_tile < niter) {
            const int ns = nt_tile % GSTAGES;   /* == (buf+2)%3: free slot */
            const int k0 = nt_tile << 4;
#pragma unroll
            for (int i = 0; i < 2; i++) {
                cpa16(&As[ns][g_row[i]][g_c4[i] * 4],
                      &A[(size_t)(bm0 + g_row[i]) * K + k0 + g_c4[i] * 4]);
                cpa16(&Bs[ns][g_row[i]][g_c4[i] * 4],
                      &B[(size_t)(bn0 + g_row[i]) * K + k0 + g_c4[i] * 4]);
            }
            CP_COMMIT();
        }
        buf = (buf + 1 == GSTAGES) ? 0 : buf + 1;
    }

#pragma unroll
    for (int mt = 0; mt < 4; mt++) {
        const int mrow = bm0 + wm + mt * 16 + r;
#pragma unroll
        for (int nt = 0; nt < 4; nt++) {
            const int col = bn0 + wn + nt * 8 + 2 * c;
            const float b0 = bias[col], b1 = bias[col + 1];
            float o0 = acc[mt][nt][0] + b0;
            float o1 = acc[mt][nt][1] + b1;
            float o2 = acc[mt][nt][2] + b0;
            float o3 = acc[mt][nt][3] + b1;
            if (RELU) {
                o0 = fmaxf(o0, 0.f); o1 = fmaxf(o1, 0.f);
                o2 = fmaxf(o2, 0.f); o3 = fmaxf(o3, 0.f);
            }
            *(float2*)&C[(size_t)mrow * N + col]       = make_float2(o0, o1);
            *(float2*)&C[(size_t)(mrow + 8) * N + col] = make_float2(o2, o3);
        }
    }
}

template<bool RELU>
__global__ __launch_bounds__(256, 2)
void gemm_tf32_nt(const float* __restrict__ A,
                  const float* __restrict__ B,
                  const float* __restrict__ bias,
                  float* __restrict__ C,
                  int M, int N, int K)
{
    extern __shared__ float gsm[];
    float (*As)[128][20] = (float(*)[128][20])gsm;
    float (*Bs)[128][20] = (float(*)[128][20])(gsm + GSTAGES * GTILE_W);
    gemm_body<RELU>(A, B, bias, C, M, N, K, As, Bs);
}

/* merged QKV: blockIdx.z selects weight/bias/output */
struct TriParams {
    const float* W[3];
    const float* b[3];
    float*       C[3];
};

__global__ __launch_bounds__(256, 2)
void gemm_tf32_qkv(const float* __restrict__ A, TriParams p,
                   int M, int N, int K)
{
    extern __shared__ float gsm[];
    float (*As)[128][20] = (float(*)[128][20])gsm;
    float (*Bs)[128][20] = (float(*)[128][20])(gsm + GSTAGES * GTILE_W);
    const int z = blockIdx.z;
    gemm_body<false>(A, p.W[z], p.b[z], p.C[z], M, N, K, As, Bs);
}

/* ------------------------------------------------------------------ */
/* Tensor-core flash attention, cp.async double-buffered KV            */
/* (unchanged from R11)                                                */
/* ------------------------------------------------------------------ */
#define AT_ST 68
#define AT_TILE_W (64 * AT_ST)

__global__ __launch_bounds__(256)
void attn_tc_kernel(const float* __restrict__ Q,
                    const float* __restrict__ K,
                    const float* __restrict__ V,
                    float* __restrict__ O)
{
    extern __shared__ float sm[];
    float (*Ks)[64][AT_ST] = (float(*)[64][AT_ST])sm;
    float (*Vs)[64][AT_ST] = (float(*)[64][AT_ST])(sm + 2 * AT_TILE_W);
    float (*Ps)[AT_ST]     = (float(*)[AT_ST])(sm + 4 * AT_TILE_W);

    const int b  = blockIdx.z, h = blockIdx.y;
    const int q0 = blockIdx.x * 128;
    const int t = threadIdx.x, w = t >> 5, lane = t & 31;
    const int r = lane >> 2, c = lane & 3;
    const size_t base = ((size_t)b * SEQ) * D_MODEL + (size_t)h * D_HEAD;

#pragma unroll
    for (int i = 0; i < 4; i++) {
        int slot = t + i * 256;
        int row = slot >> 4, c4 = slot & 15;
        cpa16(&Ks[0][row][c4 * 4], &K[base + (size_t)row * D_MODEL + c4 * 4]);
        cpa16(&Vs[0][row][c4 * 4], &V[base + (size_t)row * D_MODEL + c4 * 4]);
    }
    CP_COMMIT();

#pragma unroll
    for (int i = 0; i < 8; i++) {
        int slot = t + i * 256;
        int row = slot >> 4, c4 = slot & 15;
        *(float4*)&Ps[row][c4 * 4] =
            *(const float4*)&Q[base + (size_t)(q0 + row) * D_MODEL + c4 * 4];
    }
    __syncthreads();

    uint32_t qf[8][4];
#pragma unroll
    for (int kt = 0; kt < 8; kt++) {
        int kk = kt * 8;
        qf[kt][0] = __float_as_uint(Ps[w * 16 + r    ][kk + c    ]);
        qf[kt][1] = __float_as_uint(Ps[w * 16 + r + 8][kk + c    ]);
        qf[kt][2] = __float_as_uint(Ps[w * 16 + r    ][kk + c + 4]);
        qf[kt][3] = __float_as_uint(Ps[w * 16 + r + 8][kk + c + 4]);
    }

    float oacc[8][4];
#pragma unroll
    for (int nt = 0; nt < 8; nt++)
#pragma unroll
        for (int i = 0; i < 4; i++) oacc[nt][i] = 0.f;
    float m0 = -1e30f, m1 = -1e30f, l0 = 0.f, l1 = 0.f;
    const float scale = 0.125f;

    const int ntiles = SEQ / 64;
    for (int it = 0; it < ntiles; ++it) {
        const int buf = it & 1;
        const bool has_next = (it + 1 < ntiles);

        if (has_next) {
            const int k0n = (it + 1) * 64;
            const int nb = buf ^ 1;
#pragma unroll
            for (int i = 0; i < 4; i++) {
                int slot = t + i * 256;
                int row = slot >> 4, c4 = slot & 15;
                cpa16(&Ks[nb][row][c4 * 4],
                      &K[base + (size_t)(k0n + row) * D_MODEL + c4 * 4]);
                cpa16(&Vs[nb][row][c4 * 4],
                      &V[base + (size_t)(k0n + row) * D_MODEL + c4 * 4]);
            }
            CP_COMMIT();
            CP_WAIT1();
        } else {
            CP_WAIT0();
        }
        __syncthreads();

        float sacc[8][4];
#pragma unroll
        for (int nt = 0; nt < 8; nt++)
#pragma unroll
            for (int i = 0; i < 4; i++) sacc[nt][i] = 0.f;

#pragma unroll
        for (int kt = 0; kt < 8; kt++) {
            const int kk = kt * 8;
#pragma unroll
            for (int nt = 0; nt < 8; nt++) {
                uint32_t b0 = __float_as_uint(Ks[buf][nt * 8 + r][kk + c    ]);
                uint32_t b1 = __float_as_uint(Ks[buf][nt * 8 + r][kk + c + 4]);
                MMA_TF32(sacc[nt], qf[kt], b0, b1);
            }
        }

        float mx0 = -1e30f, mx1 = -1e30f;
#pragma unroll
        for (int nt = 0; nt < 8; nt++) {
            mx0 = fmaxf(mx0, fmaxf(sacc[nt][0], sacc[nt][1]));
            mx1 = fmaxf(mx1, fmaxf(sacc[nt][2], sacc[nt][3]));
        }
        mx0 = fmaxf(mx0, __shfl_xor_sync(0xffffffffu, mx0, 1));
        mx0 = fmaxf(mx0, __shfl_xor_sync(0xffffffffu, mx0, 2));
        mx1 = fmaxf(mx1, __shfl_xor_sync(0xffffffffu, mx1, 1));
        mx1 = fmaxf(mx1, __shfl_xor_sync(0xffffffffu, mx1, 2));

        float mn0 = fmaxf(m0, mx0 * scale);
        float mn1 = fmaxf(m1, mx1 * scale);
        float a0 = __expf(m0 - mn0), a1 = __expf(m1 - mn1);
        m0 = mn0; m1 = mn1;

        float rs0 = 0.f, rs1 = 0.f;
#pragma unroll
        for (int nt = 0; nt < 8; nt++) {
            float p00 = __expf(sacc[nt][0] * scale - mn0);
            float p01 = __expf(sacc[nt][1] * scale - mn0);
            float p10 = __expf(sacc[nt][2] * scale - mn1);
            float p11 = __expf(sacc[nt][3] * scale - mn1);
            rs0 += p00 + p01; rs1 += p10 + p11;
            *(float2*)&Ps[w * 16 + r    ][nt * 8 + 2 * c] = make_float2(p00, p01);
            *(float2*)&Ps[w * 16 + r + 8][nt * 8 + 2 * c] = make_float2(p10, p11);
        }
        rs0 += __shfl_xor_sync(0xffffffffu, rs0, 1);
        rs0 += __shfl_xor_sync(0xffffffffu, rs0, 2);
        rs1 += __shfl_xor_sync(0xffffffffu, rs1, 1);
        rs1 += __shfl_xor_sync(0xffffffffu, rs1, 2);
        l0 = l0 * a0 + rs0;
        l1 = l1 * a1 + rs1;
#pragma unroll
        for (int nt = 0; nt < 8; nt++) {
            oacc[nt][0] *= a0; oacc[nt][1] *= a0;
            oacc[nt][2] *= a1; oacc[nt][3] *= a1;
        }
        __syncwarp();

#pragma unroll
        for (int kt = 0; kt < 8; kt++) {
            const int kk = kt * 8;
            uint32_t af[4];
            af[0] = __float_as_uint(Ps[w * 16 + r    ][kk + c    ]);
            af[1] = __float_as_uint(Ps[w * 16 + r + 8][kk + c    ]);
            af[2] = __float_as_uint(Ps[w * 16 + r    ][kk + c + 4]);
            af[3] = __float_as_uint(Ps[w * 16 + r + 8][kk + c + 4]);
#pragma unroll
            for (int nt = 0; nt < 8; nt++) {
                uint32_t b0 = __float_as_uint(Vs[buf][kk + c    ][nt * 8 + r]);
                uint32_t b1 = __float_as_uint(Vs[buf][kk + c + 4][nt * 8 + r]);
                MMA_TF32(oacc[nt], af, b0, b1);
            }
        }
        __syncthreads();
    }

    const float inv0 = 1.f / l0, inv1 = 1.f / l1;
    const int row0 = q0 + w * 16 + r;
#pragma unroll
    for (int nt = 0; nt < 8; nt++) {
        const int col = nt * 8 + 2 * c;
        *(float2*)&O[base + (size_t)row0 * D_MODEL + col] =
            make_float2(oacc[nt][0] * inv0, oacc[nt][1] * inv0);
        *(float2*)&O[base + (size_t)(row0 + 8) * D_MODEL + col] =
            make_float2(oacc[nt][2] * inv1, oacc[nt][3] * inv1);
    }
}

/* ------------------------------------------------------------------ */
/* Fused residual add + LayerNorm (unchanged)                          */
/* ------------------------------------------------------------------ */
__global__ __launch_bounds__(256)
void add_ln_kernel(const float* __restrict__ A,
                   const float* __restrict__ B,
                   const float* __restrict__ gamma,
                   const float* __restrict__ beta,
                   float* __restrict__ out)
{
    const int row = blockIdx.x;
    const int t = threadIdx.x;
    const size_t roff = (size_t)row * D_MODEL;

    float4 va = *(const float4*)&A[roff + t * 4];
    float4 vb = *(const float4*)&B[roff + t * 4];
    float v0 = va.x + vb.x, v1 = va.y + vb.y, v2 = va.z + vb.z, v3 = va.w + vb.w;

    float s  = v0 + v1 + v2 + v3;
    float s2 = v0 * v0 + v1 * v1 + v2 * v2 + v3 * v3;

    __shared__ float red[2][8];
#pragma unroll
    for (int off = 16; off > 0; off >>= 1) {
        s  += __shfl_xor_sync(0xffffffffu, s,  off);
        s2 += __shfl_xor_sync(0xffffffffu, s2, off);
    }
    int warp = t >> 5, lane = t & 31;
    if (lane == 0) { red[0][warp] = s; red[1][warp] = s2; }
    __syncthreads();
    if (warp == 0) {
        s  = red[0][lane & 7];
        s2 = red[1][lane & 7];
#pragma unroll
        for (int off = 4; off > 0; off >>= 1) {
            s  += __shfl_xor_sync(0xffffffffu, s,  off);
            s2 += __shfl_xor_sync(0xffffffffu, s2, off);
        }
        if (lane == 0) { red[0][0] = s; red[1][0] = s2; }
    }
    __syncthreads();
    s  = red[0][0];
    s2 = red[1][0];

    const float inv_n = 1.f / (float)D_MODEL;
    float mu   = s * inv_n;
    float var  = s2 * inv_n - mu * mu;
    float rstd = rsqrtf(var + LN_EPS);

    float4 g4  = *(const float4*)&gamma[t * 4];
    float4 be4 = *(const float4*)&beta[t * 4];
    float4 o;
    o.x = (v0 - mu) * rstd * g4.x + be4.x;
    o.y = (v1 - mu) * rstd * g4.y + be4.y;
    o.z = (v2 - mu) * rstd * g4.z + be4.z;
    o.w = (v3 - mu) * rstd * g4.w + be4.w;
    *(float4*)&out[roff + t * 4] = o;
}

/* ------------------------------------------------------------------ */
/* Launcher                                                            */
/* ------------------------------------------------------------------ */
extern "C" void kernel_launch(void* const* d_in, const int* in_sizes, int n_in,
                              void* d_out, int out_size)
{
    const float* x   = (const float*)d_in[0];
    const float* Wq  = (const float*)d_in[1];
    const float* bq  = (const float*)d_in[2];
    const float* Wk  = (const float*)d_in[3];
    const float* bk  = (const float*)d_in[4];
    const float* Wv  = (const float*)d_in[5];
    const float* bv  = (const float*)d_in[6];
    const float* Wo  = (const float*)d_in[7];
    const float* bo  = (const float*)d_in[8];
    const float* W1  = (const float*)d_in[9];
    const float* b1  = (const float*)d_in[10];
    const float* W2  = (const float*)d_in[11];
    const float* b2  = (const float*)d_in[12];
    const float* g1  = (const float*)d_in[13];
    const float* be1 = (const float*)d_in[14];
    const float* g2  = (const float*)d_in[15];
    const float* be2 = (const float*)d_in[16];
    float* out = (float*)d_out;

    float *q, *k, *v, *att, *proj, *h, *ffn, *f2;
    cudaGetSymbolAddress((void**)&q,    g_q);
    cudaGetSymbolAddress((void**)&k,    g_k);
    cudaGetSymbolAddress((void**)&v,    g_v);
    cudaGetSymbolAddress((void**)&att,  g_att);
    cudaGetSymbolAddress((void**)&proj, g_proj);
    cudaGetSymbolAddress((void**)&h,    g_h);
    cudaGetSymbolAddress((void**)&ffn,  g_ffn);
    cudaGetSymbolAddress((void**)&f2,   g_f2);

    static int attr_set = 0;
    const int at_smem = (4 * AT_TILE_W + 128 * AT_ST) * (int)sizeof(float);
    if (!attr_set) {
        cudaFuncSetAttribute(attn_tc_kernel,
                             cudaFuncAttributeMaxDynamicSharedMemorySize, at_smem);
        cudaFuncSetAttribute(gemm_tf32_nt<false>,
                             cudaFuncAttributeMaxDynamicSharedMemorySize, GEMM_SMEM_B);
        cudaFuncSetAttribute(gemm_tf32_nt<true>,
                             cudaFuncAttributeMaxDynamicSharedMemorySize, GEMM_SMEM_B);
        cudaFuncSetAttribute(gemm_tf32_qkv,
                             cudaFuncAttributeMaxDynamicSharedMemorySize, GEMM_SMEM_B);
        attr_set = 1;
    }

    dim3 blk(256);

    /* merged QKV projections: z = 0/1/2 */
    TriParams tp;
    tp.W[0] = Wq; tp.W[1] = Wk; tp.W[2] = Wv;
    tp.b[0] = bq; tp.b[1] = bk; tp.b[2] = bv;
    tp.C[0] = q;  tp.C[1] = k;  tp.C[2] = v;
    dim3 g_qkv(D_MODEL / 128, NTOK / 128, 3);
    gemm_tf32_qkv<<<g_qkv, blk, GEMM_SMEM_B>>>(x, tp, NTOK, D_MODEL, D_MODEL);

    /* tensor-core flash attention -> att (concat layout) */
    dim3 g_at(SEQ / 128, NHEAD, BATCH);
    attn_tc_kernel<<<g_at, blk, at_smem>>>(q, k, v, att);

    /* output projection */
    dim3 g_sq(D_MODEL / 128, NTOK / 128);
    gemm_tf32_nt<false><<<g_sq, blk, GEMM_SMEM_B>>>(att, Wo, bo, proj,
                                                    NTOK, D_MODEL, D_MODEL);

    /* h = LN(x + proj) */
    add_ln_kernel<<<NTOK, blk>>>(x, proj, g1, be1, h);

    /* FFN */
    dim3 g_f1(D_FF / 128, NTOK / 128);
    gemm_tf32_nt<true ><<<g_f1, blk, GEMM_SMEM_B>>>(h,   W1, b1, ffn,
                                                    NTOK, D_FF,    D_MODEL);
    gemm_tf32_nt<false><<<g_sq, blk, GEMM_SMEM_B>>>(ffn, W2, b2, f2,
                                                    NTOK, D_MODEL, D_FF);

    /* out = LN(h + f2) */
    add_ln_kernel<<<NTOK, blk>>>(h, f2, g2, be2, out);
}

// round 14
// speedup vs baseline: 5.5149x; 1.5101x over previous
#include <cuda_runtime.h>
#include <cuda_fp16.h>
#include <cstdint>

#define D_MODEL 1024
#define NHEAD 16
#define D_HEAD 64
#define D_FF 4096
#define BATCH 2
#define SEQ 2048
#define NTOK (BATCH*SEQ)   /* 4096 tokens */
#define LN_EPS 1e-5f

/* ------------------------------------------------------------------ */
/* Scratch (static __device__ arrays; no runtime allocation)           */
/* ------------------------------------------------------------------ */
__device__ float  g_q   [(size_t)NTOK * D_MODEL];
__device__ float  g_k   [(size_t)NTOK * D_MODEL];
__device__ float  g_v   [(size_t)NTOK * D_MODEL];
__device__ float  g_proj[(size_t)NTOK * D_MODEL];
__device__ float  g_h   [(size_t)NTOK * D_MODEL];
__device__ float  g_f2  [(size_t)NTOK * D_MODEL];

__device__ __half g_x16  [(size_t)NTOK * D_MODEL];
__device__ __half g_wq16 [(size_t)D_MODEL * D_MODEL];
__device__ __half g_wk16 [(size_t)D_MODEL * D_MODEL];
__device__ __half g_wv16 [(size_t)D_MODEL * D_MODEL];
__device__ __half g_wo16 [(size_t)D_MODEL * D_MODEL];
__device__ __half g_w116 [(size_t)D_FF * D_MODEL];
__device__ __half g_w216 [(size_t)D_MODEL * D_FF];
__device__ __half g_att16[(size_t)NTOK * D_MODEL];
__device__ __half g_h16  [(size_t)NTOK * D_MODEL];
__device__ __half g_ffn16[(size_t)NTOK * D_FF];

/* tf32 MMA (attention), fp32 bits fed directly */
#define MMA_TF32(acc, a, b0, b1)                                        \
    asm volatile(                                                       \
        "mma.sync.aligned.m16n8k8.row.col.f32.tf32.tf32.f32 "           \
        "{%0,%1,%2,%3}, {%4,%5,%6,%7}, {%8,%9}, {%0,%1,%2,%3};\n"       \
        : "+f"(acc[0]), "+f"(acc[1]), "+f"(acc[2]), "+f"(acc[3])        \
        : "r"(a[0]), "r"(a[1]), "r"(a[2]), "r"(a[3]), "r"(b0), "r"(b1))

/* fp16 MMA (GEMMs), fp32 accumulate */
#define MMA_F16(acc, a, b0, b1)                                         \
    asm volatile(                                                       \
        "mma.sync.aligned.m16n8k16.row.col.f32.f16.f16.f32 "            \
        "{%0,%1,%2,%3}, {%4,%5,%6,%7}, {%8,%9}, {%0,%1,%2,%3};\n"       \
        : "+f"(acc[0]), "+f"(acc[1]), "+f"(acc[2]), "+f"(acc[3])        \
        : "r"(a[0]), "r"(a[1]), "r"(a[2]), "r"(a[3]), "r"(b0), "r"(b1))

__device__ __forceinline__ void cpa16(void* s, const void* g) {
    uint32_t sa = (uint32_t)__cvta_generic_to_shared(s);
    asm volatile("cp.async.cg.shared.global [%0], [%1], 16;" :: "r"(sa), "l"(g));
}
#define CP_COMMIT() asm volatile("cp.async.commit_group;")
#define CP_WAIT0()  asm volatile("cp.async.wait_group 0;")
#define CP_WAIT1()  asm volatile("cp.async.wait_group 1;")

/* ------------------------------------------------------------------ */
/* fp32 -> fp16 convert                                                */
/* ------------------------------------------------------------------ */
__global__ __launch_bounds__(256)
void f2h_kernel(const float* __restrict__ src, __half* __restrict__ dst, int n)
{
    int i = (blockIdx.x * 256 + threadIdx.x) * 4;
    if (i < n) {
        float4 v = *(const float4*)&src[i];
        *(__half2*)&dst[i]     = __floats2half2_rn(v.x, v.y);
        *(__half2*)&dst[i + 2] = __floats2half2_rn(v.z, v.w);
    }
}

/* ------------------------------------------------------------------ */
/* fp16 GEMM:  C[M,N] = A[M,K] @ B[N,K]^T + bias  (opt ReLU, opt h16)  */
/* BM=BN=128, BK=32, 256 thr, warp tile 64x32, m16n8k16               */
/* 3-stage cp.async ring.  SMEM stride 40 halfs (bank-clean frags).    */
/* ------------------------------------------------------------------ */
#define GST 40                       /* halfs per smem row */
#define GTILE_H (128 * GST)          /* halfs per operand tile */
#define GSTAGES 3
#define GEMM_SMEM_B (GSTAGES * 2 * GTILE_H * (int)sizeof(__half))  /* 61440 */

template<bool RELU, bool HOUT>
__device__ __forceinline__
void gemm_h_body(const __half* __restrict__ A,
                 const __half* __restrict__ B,
                 const float* __restrict__ bias,
                 float* __restrict__ C,
                 __half* __restrict__ C16,
                 int N, int K, __half* smem)
{
    const int bm0 = blockIdx.y * 128;
    const int bn0 = blockIdx.x * 128;
    const int t    = threadIdx.x;
    const int warp = t >> 5, lane = t & 31;
    const int wm = (warp >> 2) * 64;
    const int wn = (warp & 3) * 32;
    const int r  = lane >> 2;
    const int c  = lane & 3;

    __half* As = smem;
    __half* Bs = smem + GSTAGES * GTILE_H;

    float acc[4][4][4];
#pragma unroll
    for (int mt = 0; mt < 4; mt++)
#pragma unroll
        for (int nt = 0; nt < 4; nt++)
#pragma unroll
            for (int i = 0; i < 4; i++) acc[mt][nt][i] = 0.f;

    int g_row[2], g_sg[2];
#pragma unroll
    for (int i = 0; i < 2; i++) {
        int slot = t + i * 256;      /* 0..511 */
        g_row[i] = slot >> 2;        /* 0..127 */
        g_sg[i]  = slot & 3;         /* 0..3 -> 8-half segment */
    }

    const int niter = K >> 5;        /* BK=32 */

    /* prologue: issue tiles 0,1 into stages 0,1 */
#pragma unroll
    for (int s = 0; s < GSTAGES - 1; ++s) {
        const int k0 = s << 5;
#pragma unroll
        for (int i = 0; i < 2; i++) {
            cpa16(&As[s * GTILE_H + g_row[i] * GST + g_sg[i] * 8],
                  A + (size_t)(bm0 + g_row[i]) * K + k0 + g_sg[i] * 8);
            cpa16(&Bs[s * GTILE_H + g_row[i] * GST + g_sg[i] * 8],
                  B + (size_t)(bn0 + g_row[i]) * K + k0 + g_sg[i] * 8);
        }
        CP_COMMIT();
    }

    int buf = 0;
    for (int it = 0; it < niter; ++it) {
        CP_WAIT1();                  /* tile `it` complete */
        __syncthreads();

        const __half* Ab = As + buf * GTILE_H;
        const __half* Bb = Bs + buf * GTILE_H;
#pragma unroll
        for (int ks = 0; ks < 2; ++ks) {
            const int kk = ks * 16;
            uint32_t af[4][4], bf[4][2];
#pragma unroll
            for (int mt = 0; mt < 4; mt++) {
                const int m0 = wm + mt * 16;
                af[mt][0] = *(const uint32_t*)&Ab[(m0 + r    ) * GST + kk + 2*c    ];
                af[mt][1] = *(const uint32_t*)&Ab[(m0 + r + 8) * GST + kk + 2*c    ];
                af[mt][2] = *(const uint32_t*)&Ab[(m0 + r    ) * GST + kk + 2*c + 8];
                af[mt][3] = *(const uint32_t*)&Ab[(m0 + r + 8) * GST + kk + 2*c + 8];
            }
#pragma unroll
            for (int nt = 0; nt < 4; nt++) {
                const int n0 = wn + nt * 8;
                bf[nt][0] = *(const uint32_t*)&Bb[(n0 + r) * GST + kk + 2*c    ];
                bf[nt][1] = *(const uint32_t*)&Bb[(n0 + r) * GST + kk + 2*c + 8];
            }
#pragma unroll
            for (int mt = 0; mt < 4; mt++)
#pragma unroll
                for (int nt = 0; nt < 4; nt++)
                    MMA_F16(acc[mt][nt], af[mt], bf[nt][0], bf[nt][1]);
        }

        /* prefetch tile it+2 into free slot (all warps past compute(it-1)) */
        const int nt_tile = it + GSTAGES - 1;
        if (nt_tile < niter) {
            const int ns = nt_tile % GSTAGES;
            const int k0 = nt_tile << 5;
#pragma unroll
            for (int i = 0; i < 2; i++) {
                cpa16(&As[ns * GTILE_H + g_row[i] * GST + g_sg[i] * 8],
                      A + (size_t)(bm0 + g_row[i]) * K + k0 + g_sg[i] * 8);
                cpa16(&Bs[ns * GTILE_H + g_row[i] * GST + g_sg[i] * 8],
                      B + (size_t)(bn0 + g_row[i]) * K + k0 + g_sg[i] * 8);
            }
            CP_COMMIT();
        }
        buf = (buf + 1 == GSTAGES) ? 0 : buf + 1;
    }

#pragma unroll
    for (int mt = 0; mt < 4; mt++) {
        const int mrow = bm0 + wm + mt * 16 + r;
#pragma unroll
        for (int nt = 0; nt < 4; nt++) {
            const int col = bn0 + wn + nt * 8 + 2 * c;
            const float b0 = bias[col], b1 = bias[col + 1];
            float o0 = acc[mt][nt][0] + b0;
            float o1 = acc[mt][nt][1] + b1;
            float o2 = acc[mt][nt][2] + b0;
            float o3 = acc[mt][nt][3] + b1;
            if (RELU) {
                o0 = fmaxf(o0, 0.f); o1 = fmaxf(o1, 0.f);
                o2 = fmaxf(o2, 0.f); o3 = fmaxf(o3, 0.f);
            }
            if (HOUT) {
                *(__half2*)&C16[(size_t)mrow * N + col]       = __floats2half2_rn(o0, o1);
                *(__half2*)&C16[(size_t)(mrow + 8) * N + col] = __floats2half2_rn(o2, o3);
            } else {
                *(float2*)&C[(size_t)mrow * N + col]       = make_float2(o0, o1);
                *(float2*)&C[(size_t)(mrow + 8) * N + col] = make_float2(o2, o3);
            }
        }
    }
}

template<bool RELU, bool HOUT>
__global__ __launch_bounds__(256, 2)
void gemm_h(const __half* __restrict__ A, const __half* __restrict__ B,
            const float* __restrict__ bias, float* __restrict__ C,
            __half* __restrict__ C16, int N, int K)
{
    extern __shared__ __half hsm[];
    gemm_h_body<RELU, HOUT>(A, B, bias, C, C16, N, K, hsm);
}

struct TriParams {
    const __half* W[3];
    const float*  b[3];
    float*        C[3];
};

__global__ __launch_bounds__(256, 2)
void gemm_h_qkv(const __half* __restrict__ A, TriParams p, int N, int K)
{
    extern __shared__ __half hsm[];
    const int z = blockIdx.z;
    gemm_h_body<false, false>(A, p.W[z], p.b[z], p.C[z], (__half*)0, N, K, hsm);
}

/* ------------------------------------------------------------------ */
/* Tensor-core flash attention (tf32, validated) — epilogue now fp16.  */
/* ------------------------------------------------------------------ */
#define AT_ST 68
#define AT_TILE_W (64 * AT_ST)

__global__ __launch_bounds__(256)
void attn_tc_kernel(const float* __restrict__ Q,
                    const float* __restrict__ K,
                    const float* __restrict__ V,
                    __half* __restrict__ O16)
{
    extern __shared__ float sm[];
    float (*Ks)[64][AT_ST] = (float(*)[64][AT_ST])sm;
    float (*Vs)[64][AT_ST] = (float(*)[64][AT_ST])(sm + 2 * AT_TILE_W);
    float (*Ps)[AT_ST]     = (float(*)[AT_ST])(sm + 4 * AT_TILE_W);

    const int b  = blockIdx.z, h = blockIdx.y;
    const int q0 = blockIdx.x * 128;
    const int t = threadIdx.x, w = t >> 5, lane = t & 31;
    const int r = lane >> 2, c = lane & 3;
    const size_t base = ((size_t)b * SEQ) * D_MODEL + (size_t)h * D_HEAD;

#pragma unroll
    for (int i = 0; i < 4; i++) {
        int slot = t + i * 256;
        int row = slot >> 4, c4 = slot & 15;
        cpa16(&Ks[0][row][c4 * 4], &K[base + (size_t)row * D_MODEL + c4 * 4]);
        cpa16(&Vs[0][row][c4 * 4], &V[base + (size_t)row * D_MODEL + c4 * 4]);
    }
    CP_COMMIT();

#pragma unroll
    for (int i = 0; i < 8; i++) {
        int slot = t + i * 256;
        int row = slot >> 4, c4 = slot & 15;
        *(float4*)&Ps[row][c4 * 4] =
            *(const float4*)&Q[base + (size_t)(q0 + row) * D_MODEL + c4 * 4];
    }
    __syncthreads();

    uint32_t qf[8][4];
#pragma unroll
    for (int kt = 0; kt < 8; kt++) {
        int kk = kt * 8;
        qf[kt][0] = __float_as_uint(Ps[w * 16 + r    ][kk + c    ]);
        qf[kt][1] = __float_as_uint(Ps[w * 16 + r + 8][kk + c    ]);
        qf[kt][2] = __float_as_uint(Ps[w * 16 + r    ][kk + c + 4]);
        qf[kt][3] = __float_as_uint(Ps[w * 16 + r + 8][kk + c + 4]);
    }

    float oacc[8][4];
#pragma unroll
    for (int nt = 0; nt < 8; nt++)
#pragma unroll
        for (int i = 0; i < 4; i++) oacc[nt][i] = 0.f;
    float m0 = -1e30f, m1 = -1e30f, l0 = 0.f, l1 = 0.f;
    const float scale = 0.125f;

    const int ntiles = SEQ / 64;
    for (int it = 0; it < ntiles; ++it) {
        const int buf = it & 1;
        const bool has_next = (it + 1 < ntiles);

        if (has_next) {
            const int k0n = (it + 1) * 64;
            const int nb = buf ^ 1;
#pragma unroll
            for (int i = 0; i < 4; i++) {
                int slot = t + i * 256;
                int row = slot >> 4, c4 = slot & 15;
                cpa16(&Ks[nb][row][c4 * 4],
                      &K[base + (size_t)(k0n + row) * D_MODEL + c4 * 4]);
                cpa16(&Vs[nb][row][c4 * 4],
                      &V[base + (size_t)(k0n + row) * D_MODEL + c4 * 4]);
            }
            CP_COMMIT();
            CP_WAIT1();
        } else {
            CP_WAIT0();
        }
        __syncthreads();

        float sacc[8][4];
#pragma unroll
        for (int nt = 0; nt < 8; nt++)
#pragma unroll
            for (int i = 0; i < 4; i++) sacc[nt][i] = 0.f;

#pragma unroll
        for (int kt = 0; kt < 8; kt++) {
            const int kk = kt * 8;
#pragma unroll
            for (int nt = 0; nt < 8; nt++) {
                uint32_t b0 = __float_as_uint(Ks[buf][nt * 8 + r][kk + c    ]);
                uint32_t b1 = __float_as_uint(Ks[buf][nt * 8 + r][kk + c + 4]);
                MMA_TF32(sacc[nt], qf[kt], b0, b1);
            }
        }

        float mx0 = -1e30f, mx1 = -1e30f;
#pragma unroll
        for (int nt = 0; nt < 8; nt++) {
            mx0 = fmaxf(mx0, fmaxf(sacc[nt][0], sacc[nt][1]));
            mx1 = fmaxf(mx1, fmaxf(sacc[nt][2], sacc[nt][3]));
        }
        mx0 = fmaxf(mx0, __shfl_xor_sync(0xffffffffu, mx0, 1));
        mx0 = fmaxf(mx0, __shfl_xor_sync(0xffffffffu, mx0, 2));
        mx1 = fmaxf(mx1, __shfl_xor_sync(0xffffffffu, mx1, 1));
        mx1 = fmaxf(mx1, __shfl_xor_sync(0xffffffffu, mx1, 2));

        float mn0 = fmaxf(m0, mx0 * scale);
        float mn1 = fmaxf(m1, mx1 * scale);
        float a0 = __expf(m0 - mn0), a1 = __expf(m1 - mn1);
        m0 = mn0; m1 = mn1;

        float rs0 = 0.f, rs1 = 0.f;
#pragma unroll
        for (int nt = 0; nt < 8; nt++) {
            float p00 = __expf(sacc[nt][0] * scale - mn0);
            float p01 = __expf(sacc[nt][1] * scale - mn0);
            float p10 = __expf(sacc[nt][2] * scale - mn1);
            float p11 = __expf(sacc[nt][3] * scale - mn1);
            rs0 += p00 + p01; rs1 += p10 + p11;
            *(float2*)&Ps[w * 16 + r    ][nt * 8 + 2 * c] = make_float2(p00, p01);
            *(float2*)&Ps[w * 16 + r + 8][nt * 8 + 2 * c] = make_float2(p10, p11);
        }
        rs0 += __shfl_xor_sync(0xffffffffu, rs0, 1);
        rs0 += __shfl_xor_sync(0xffffffffu, rs0, 2);
        rs1 += __shfl_xor_sync(0xffffffffu, rs1, 1);
        rs1 += __shfl_xor_sync(0xffffffffu, rs1, 2);
        l0 = l0 * a0 + rs0;
        l1 = l1 * a1 + rs1;
#pragma unroll
        for (int nt = 0; nt < 8; nt++) {
            oacc[nt][0] *= a0; oacc[nt][1] *= a0;
            oacc[nt][2] *= a1; oacc[nt][3] *= a1;
        }
        __syncwarp();

#pragma unroll
        for (int kt = 0; kt < 8; kt++) {
            const int kk = kt * 8;
            uint32_t af[4];
            af[0] = __float_as_uint(Ps[w * 16 + r    ][kk + c    ]);
            af[1] = __float_as_uint(Ps[w * 16 + r + 8][kk + c    ]);
            af[2] = __float_as_uint(Ps[w * 16 + r    ][kk + c + 4]);
            af[3] = __float_as_uint(Ps[w * 16 + r + 8][kk + c + 4]);
#pragma unroll
            for (int nt = 0; nt < 8; nt++) {
                uint32_t b0 = __float_as_uint(Vs[buf][kk + c    ][nt * 8 + r]);
                uint32_t b1 = __float_as_uint(Vs[buf][kk + c + 4][nt * 8 + r]);
                MMA_TF32(oacc[nt], af, b0, b1);
            }
        }
        __syncthreads();
    }

    const float inv0 = 1.f / l0, inv1 = 1.f / l1;
    const int row0 = q0 + w * 16 + r;
#pragma unroll
    for (int nt = 0; nt < 8; nt++) {
        const int col = nt * 8 + 2 * c;
        *(__half2*)&O16[base + (size_t)row0 * D_MODEL + col] =
            __floats2half2_rn(oacc[nt][0] * inv0, oacc[nt][1] * inv0);
        *(__half2*)&O16[base + (size_t)(row0 + 8) * D_MODEL + col] =
            __floats2half2_rn(oacc[nt][2] * inv1, oacc[nt][3] * inv1);
    }
}

/* ------------------------------------------------------------------ */
/* Fused residual add + LayerNorm; optional fp16 mirror output         */
/* ------------------------------------------------------------------ */
__global__ __launch_bounds__(256)
void add_ln_kernel(const float* __restrict__ A,
                   const float* __restrict__ B,
                   const float* __restrict__ gamma,
                   const float* __restrict__ beta,
                   float* __restrict__ out,
                   __half* __restrict__ out16)
{
    const int row = blockIdx.x;
    const int t = threadIdx.x;
    const size_t roff = (size_t)row * D_MODEL;

    float4 va = *(const float4*)&A[roff + t * 4];
    float4 vb = *(const float4*)&B[roff + t * 4];
    float v0 = va.x + vb.x, v1 = va.y + vb.y, v2 = va.z + vb.z, v3 = va.w + vb.w;

    float s  = v0 + v1 + v2 + v3;
    float s2 = v0 * v0 + v1 * v1 + v2 * v2 + v3 * v3;

    __shared__ float red[2][8];
#pragma unroll
    for (int off = 16; off > 0; off >>= 1) {
        s  += __shfl_xor_sync(0xffffffffu, s,  off);
        s2 += __shfl_xor_sync(0xffffffffu, s2, off);
    }
    int warp = t >> 5, lane = t & 31;
    if (lane == 0) { red[0][warp] = s; red[1][warp] = s2; }
    __syncthreads();
    if (warp == 0) {
        s  = red[0][lane & 7];
        s2 = red[1][lane & 7];
#pragma unroll
        for (int off = 4; off > 0; off >>= 1) {
            s  += __shfl_xor_sync(0xffffffffu, s,  off);
            s2 += __shfl_xor_sync(0xffffffffu, s2, off);
        }
        if (lane == 0) { red[0][0] = s; red[1][0] = s2; }
    }
    __syncthreads();
    s  = red[0][0];
    s2 = red[1][0];

    const float inv_n = 1.f / (float)D_MODEL;
    float mu   = s * inv_n;
    float var  = s2 * inv_n - mu * mu;
    float rstd = rsqrtf(var + LN_EPS);

    float4 g4  = *(const float4*)&gamma[t * 4];
    float4 be4 = *(const float4*)&beta[t * 4];
    float4 o;
    o.x = (v0 - mu) * rstd * g4.x + be4.x;
    o.y = (v1 - mu) * rstd * g4.y + be4.y;
    o.z = (v2 - mu) * rstd * g4.z + be4.z;
    o.w = (v3 - mu) * rstd * g4.w + be4.w;
    *(float4*)&out[roff + t * 4] = o;
    if (out16) {
        *(__half2*)&out16[roff + t * 4]     = __floats2half2_rn(o.x, o.y);
        *(__half2*)&out16[roff + t * 4 + 2] = __floats2half2_rn(o.z, o.w);
    }
}

/* ------------------------------------------------------------------ */
/* Launcher                                                            */
/* ------------------------------------------------------------------ */
extern "C" void kernel_launch(void* const* d_in, const int* in_sizes, int n_in,
                              void* d_out, int out_size)
{
    const float* x   = (const float*)d_in[0];
    const float* Wq  = (const float*)d_in[1];
    const float* bq  = (const float*)d_in[2];
    const float* Wk  = (const float*)d_in[3];
    const float* bk  = (const float*)d_in[4];
    const float* Wv  = (const float*)d_in[5];
    const float* bv  = (const float*)d_in[6];
    const float* Wo  = (const float*)d_in[7];
    const float* bo  = (const float*)d_in[8];
    const float* W1  = (const float*)d_in[9];
    const float* b1  = (const float*)d_in[10];
    const float* W2  = (const float*)d_in[11];
    const float* b2  = (const float*)d_in[12];
    const float* g1  = (const float*)d_in[13];
    const float* be1 = (const float*)d_in[14];
    const float* g2  = (const float*)d_in[15];
    const float* be2 = (const float*)d_in[16];
    float* out = (float*)d_out;

    float *q, *k, *v, *proj, *h, *f2;
    cudaGetSymbolAddress((void**)&q,    g_q);
    cudaGetSymbolAddress((void**)&k,    g_k);
    cudaGetSymbolAddress((void**)&v,    g_v);
    cudaGetSymbolAddress((void**)&proj, g_proj);
    cudaGetSymbolAddress((void**)&h,    g_h);
    cudaGetSymbolAddress((void**)&f2,   g_f2);

    __half *x16, *wq16, *wk16, *wv16, *wo16, *w116, *w216, *att16, *h16, *ffn16;
    cudaGetSymbolAddress((void**)&x16,   g_x16);
    cudaGetSymbolAddress((void**)&wq16,  g_wq16);
    cudaGetSymbolAddress((void**)&wk16,  g_wk16);
    cudaGetSymbolAddress((void**)&wv16,  g_wv16);
    cudaGetSymbolAddress((void**)&wo16,  g_wo16);
    cudaGetSymbolAddress((void**)&w116,  g_w116);
    cudaGetSymbolAddress((void**)&w216,  g_w216);
    cudaGetSymbolAddress((void**)&att16, g_att16);
    cudaGetSymbolAddress((void**)&h16,   g_h16);
    cudaGetSymbolAddress((void**)&ffn16, g_ffn16);

    static int attr_set = 0;
    const int at_smem = (4 * AT_TILE_W + 128 * AT_ST) * (int)sizeof(float);
    if (!attr_set) {
        cudaFuncSetAttribute(attn_tc_kernel,
                             cudaFuncAttributeMaxDynamicSharedMemorySize, at_smem);
        cudaFuncSetAttribute(gemm_h<false, false>,
                             cudaFuncAttributeMaxDynamicSharedMemorySize, GEMM_SMEM_B);
        cudaFuncSetAttribute(gemm_h<true, true>,
                             cudaFuncAttributeMaxDynamicSharedMemorySize, GEMM_SMEM_B);
        cudaFuncSetAttribute(gemm_h_qkv,
                             cudaFuncAttributeMaxDynamicSharedMemorySize, GEMM_SMEM_B);
        attr_set = 1;
    }

    dim3 blk(256);

    /* convert inputs + weights to fp16 */
    f2h_kernel<<<(NTOK*D_MODEL)/1024, blk>>>(x,  x16,  NTOK*D_MODEL);
    f2h_kernel<<<(D_MODEL*D_MODEL)/1024, blk>>>(Wq, wq16, D_MODEL*D_MODEL);
    f2h_kernel<<<(D_MODEL*D_MODEL)/1024, blk>>>(Wk, wk16, D_MODEL*D_MODEL);
    f2h_kernel<<<(D_MODEL*D_MODEL)/1024, blk>>>(Wv, wv16, D_MODEL*D_MODEL);
    f2h_kernel<<<(D_MODEL*D_MODEL)/1024, blk>>>(Wo, wo16, D_MODEL*D_MODEL);
    f2h_kernel<<<(D_FF*D_MODEL)/1024, blk>>>(W1, w116, D_FF*D_MODEL);
    f2h_kernel<<<(D_MODEL*D_FF)/1024, blk>>>(W2, w216, D_MODEL*D_FF);

    /* merged QKV projections -> fp32 q,k,v */
    TriParams tp;
    tp.W[0] = wq16; tp.W[1] = wk16; tp.W[2] = wv16;
    tp.b[0] = bq;   tp.b[1] = bk;   tp.b[2] = bv;
    tp.C[0] = q;    tp.C[1] = k;    tp.C[2] = v;
    dim3 g_qkv(D_MODEL / 128, NTOK / 128, 3);
    gemm_h_qkv<<<g_qkv, blk, GEMM_SMEM_B>>>(x16, tp, D_MODEL, D_MODEL);

    /* attention -> att16 (fp16 concat layout) */
    dim3 g_at(SEQ / 128, NHEAD, BATCH);
    attn_tc_kernel<<<g_at, blk, at_smem>>>(q, k, v, att16);

    /* output projection (fp16 in, fp32 out) */
    dim3 g_sq(D_MODEL / 128, NTOK / 128);
    gemm_h<false, false><<<g_sq, blk, GEMM_SMEM_B>>>(att16, wo16, bo, proj,
                                                     (__half*)0, D_MODEL, D_MODEL);

    /* h = LN(x + proj), also h16 */
    add_ln_kernel<<<NTOK, blk>>>(x, proj, g1, be1, h, h16);

    /* FFN1 (ReLU, fp16 out) */
    dim3 g_f1(D_FF / 128, NTOK / 128);
    gemm_h<true, true><<<g_f1, blk, GEMM_SMEM_B>>>(h16, w116, b1, (float*)0,
                                                   ffn16, D_FF, D_MODEL);
    /* FFN2 (fp32 out) */
    gemm_h<false, false><<<g_sq, blk, GEMM_SMEM_B>>>(ffn16, w216, b2, f2,
                                                     (__half*)0, D_MODEL, D_FF);

    /* out = LN(h + f2) */
    add_ln_kernel<<<NTOK, blk>>>(h, f2, g2, be2, out, (__half*)0);
}

// round 15
// speedup vs baseline: 7.2976x; 1.3232x over previous
#include <cuda_runtime.h>
#include <cuda_fp16.h>
#include <cstdint>

#define D_MODEL 1024
#define NHEAD 16
#define D_HEAD 64
#define D_FF 4096
#define BATCH 2
#define SEQ 2048
#define NTOK (BATCH*SEQ)   /* 4096 tokens */
#define LN_EPS 1e-5f

/* ------------------------------------------------------------------ */
/* Scratch (static __device__ arrays; no runtime allocation)           */
/* ------------------------------------------------------------------ */
__device__ float  g_proj[(size_t)NTOK * D_MODEL];
__device__ float  g_h   [(size_t)NTOK * D_MODEL];
__device__ float  g_f2  [(size_t)NTOK * D_MODEL];

__device__ __half g_x16  [(size_t)NTOK * D_MODEL];
__device__ __half g_wq16 [(size_t)D_MODEL * D_MODEL];
__device__ __half g_wk16 [(size_t)D_MODEL * D_MODEL];
__device__ __half g_wv16 [(size_t)D_MODEL * D_MODEL];
__device__ __half g_wo16 [(size_t)D_MODEL * D_MODEL];
__device__ __half g_w116 [(size_t)D_FF * D_MODEL];
__device__ __half g_w216 [(size_t)D_MODEL * D_FF];
__device__ __half g_q16  [(size_t)NTOK * D_MODEL];
__device__ __half g_k16  [(size_t)NTOK * D_MODEL];
__device__ __half g_v16  [(size_t)NTOK * D_MODEL];
__device__ __half g_att16[(size_t)NTOK * D_MODEL];
__device__ __half g_h16  [(size_t)NTOK * D_MODEL];
__device__ __half g_ffn16[(size_t)NTOK * D_FF];

/* fp16 MMA, fp32 accumulate */
#define MMA_F16(acc, a, b0, b1)                                         \
    asm volatile(                                                       \
        "mma.sync.aligned.m16n8k16.row.col.f32.f16.f16.f32 "            \
        "{%0,%1,%2,%3}, {%4,%5,%6,%7}, {%8,%9}, {%0,%1,%2,%3};\n"       \
        : "+f"(acc[0]), "+f"(acc[1]), "+f"(acc[2]), "+f"(acc[3])        \
        : "r"(a[0]), "r"(a[1]), "r"(a[2]), "r"(a[3]), "r"(b0), "r"(b1))

#define LDSM_X4_TRANS(d0, d1, d2, d3, addr)                             \
    asm volatile(                                                       \
        "ldmatrix.sync.aligned.m8n8.x4.trans.shared.b16 "               \
        "{%0,%1,%2,%3}, [%4];"                                          \
        : "=r"(d0), "=r"(d1), "=r"(d2), "=r"(d3) : "r"(addr))

__device__ __forceinline__ void cpa16(void* s, const void* g) {
    uint32_t sa = (uint32_t)__cvta_generic_to_shared(s);
    asm volatile("cp.async.cg.shared.global [%0], [%1], 16;" :: "r"(sa), "l"(g));
}
#define CP_COMMIT() asm volatile("cp.async.commit_group;")
#define CP_WAIT0()  asm volatile("cp.async.wait_group 0;")
#define CP_WAIT1()  asm volatile("cp.async.wait_group 1;")

__device__ __forceinline__ uint32_t packh2(float a, float b) {
    __half2 h = __floats2half2_rn(a, b);
    return *(uint32_t*)&h;
}

/* ------------------------------------------------------------------ */
/* fp32 -> fp16 convert                                                */
/* ------------------------------------------------------------------ */
__global__ __launch_bounds__(256)
void f2h_kernel(const float* __restrict__ src, __half* __restrict__ dst, int n)
{
    int i = (blockIdx.x * 256 + threadIdx.x) * 4;
    if (i < n) {
        float4 v = *(const float4*)&src[i];
        *(__half2*)&dst[i]     = __floats2half2_rn(v.x, v.y);
        *(__half2*)&dst[i + 2] = __floats2half2_rn(v.z, v.w);
    }
}

/* ------------------------------------------------------------------ */
/* fp16 GEMM:  C[M,N] = A[M,K] @ B[N,K]^T + bias (opt ReLU, opt fp16)  */
/* (validated R14; unchanged)                                          */
/* ------------------------------------------------------------------ */
#define GST 40
#define GTILE_H (128 * GST)
#define GSTAGES 3
#define GEMM_SMEM_B (GSTAGES * 2 * GTILE_H * (int)sizeof(__half))

template<bool RELU, bool HOUT>
__device__ __forceinline__
void gemm_h_body(const __half* __restrict__ A,
                 const __half* __restrict__ B,
                 const float* __restrict__ bias,
                 float* __restrict__ C,
                 __half* __restrict__ C16,
                 int N, int K, __half* smem)
{
    const int bm0 = blockIdx.y * 128;
    const int bn0 = blockIdx.x * 128;
    const int t    = threadIdx.x;
    const int warp = t >> 5, lane = t & 31;
    const int wm = (warp >> 2) * 64;
    const int wn = (warp & 3) * 32;
    const int r  = lane >> 2;
    const int c  = lane & 3;

    __half* As = smem;
    __half* Bs = smem + GSTAGES * GTILE_H;

    float acc[4][4][4];
#pragma unroll
    for (int mt = 0; mt < 4; mt++)
#pragma unroll
        for (int nt = 0; nt < 4; nt++)
#pragma unroll
            for (int i = 0; i < 4; i++) acc[mt][nt][i] = 0.f;

    int g_row[2], g_sg[2];
#pragma unroll
    for (int i = 0; i < 2; i++) {
        int slot = t + i * 256;
        g_row[i] = slot >> 2;
        g_sg[i]  = slot & 3;
    }

    const int niter = K >> 5;

#pragma unroll
    for (int s = 0; s < GSTAGES - 1; ++s) {
        const int k0 = s << 5;
#pragma unroll
        for (int i = 0; i < 2; i++) {
            cpa16(&As[s * GTILE_H + g_row[i] * GST + g_sg[i] * 8],
                  A + (size_t)(bm0 + g_row[i]) * K + k0 + g_sg[i] * 8);
            cpa16(&Bs[s * GTILE_H + g_row[i] * GST + g_sg[i] * 8],
                  B + (size_t)(bn0 + g_row[i]) * K + k0 + g_sg[i] * 8);
        }
        CP_COMMIT();
    }

    int buf = 0;
    for (int it = 0; it < niter; ++it) {
        CP_WAIT1();
        __syncthreads();

        const __half* Ab = As + buf * GTILE_H;
        const __half* Bb = Bs + buf * GTILE_H;
#pragma unroll
        for (int ks = 0; ks < 2; ++ks) {
            const int kk = ks * 16;
            uint32_t af[4][4], bf[4][2];
#pragma unroll
            for (int mt = 0; mt < 4; mt++) {
                const int m0 = wm + mt * 16;
                af[mt][0] = *(const uint32_t*)&Ab[(m0 + r    ) * GST + kk + 2*c    ];
                af[mt][1] = *(const uint32_t*)&Ab[(m0 + r + 8) * GST + kk + 2*c    ];
                af[mt][2] = *(const uint32_t*)&Ab[(m0 + r    ) * GST + kk + 2*c + 8];
                af[mt][3] = *(const uint32_t*)&Ab[(m0 + r + 8) * GST + kk + 2*c + 8];
            }
#pragma unroll
            for (int nt = 0; nt < 4; nt++) {
                const int n0 = wn + nt * 8;
                bf[nt][0] = *(const uint32_t*)&Bb[(n0 + r) * GST + kk + 2*c    ];
                bf[nt][1] = *(const uint32_t*)&Bb[(n0 + r) * GST + kk + 2*c + 8];
            }
#pragma unroll
            for (int mt = 0; mt < 4; mt++)
#pragma unroll
                for (int nt = 0; nt < 4; nt++)
                    MMA_F16(acc[mt][nt], af[mt], bf[nt][0], bf[nt][1]);
        }

        const int nt_tile = it + GSTAGES - 1;
        if (nt_tile < niter) {
            const int ns = nt_tile % GSTAGES;
            const int k0 = nt_tile << 5;
#pragma unroll
            for (int i = 0; i < 2; i++) {
                cpa16(&As[ns * GTILE_H + g_row[i] * GST + g_sg[i] * 8],
                      A + (size_t)(bm0 + g_row[i]) * K + k0 + g_sg[i] * 8);
                cpa16(&Bs[ns * GTILE_H + g_row[i] * GST + g_sg[i] * 8],
                      B + (size_t)(bn0 + g_row[i]) * K + k0 + g_sg[i] * 8);
            }
            CP_COMMIT();
        }
        buf = (buf + 1 == GSTAGES) ? 0 : buf + 1;
    }

#pragma unroll
    for (int mt = 0; mt < 4; mt++) {
        const int mrow = bm0 + wm + mt * 16 + r;
#pragma unroll
        for (int nt = 0; nt < 4; nt++) {
            const int col = bn0 + wn + nt * 8 + 2 * c;
            const float b0 = bias[col], b1 = bias[col + 1];
            float o0 = acc[mt][nt][0] + b0;
            float o1 = acc[mt][nt][1] + b1;
            float o2 = acc[mt][nt][2] + b0;
            float o3 = acc[mt][nt][3] + b1;
            if (RELU) {
                o0 = fmaxf(o0, 0.f); o1 = fmaxf(o1, 0.f);
                o2 = fmaxf(o2, 0.f); o3 = fmaxf(o3, 0.f);
            }
            if (HOUT) {
                *(__half2*)&C16[(size_t)mrow * N + col]       = __floats2half2_rn(o0, o1);
                *(__half2*)&C16[(size_t)(mrow + 8) * N + col] = __floats2half2_rn(o2, o3);
            } else {
                *(float2*)&C[(size_t)mrow * N + col]       = make_float2(o0, o1);
                *(float2*)&C[(size_t)(mrow + 8) * N + col] = make_float2(o2, o3);
            }
        }
    }
}

template<bool RELU, bool HOUT>
__global__ __launch_bounds__(256, 2)
void gemm_h(const __half* __restrict__ A, const __half* __restrict__ B,
            const float* __restrict__ bias, float* __restrict__ C,
            __half* __restrict__ C16, int N, int K)
{
    extern __shared__ __half hsm[];
    gemm_h_body<RELU, HOUT>(A, B, bias, C, C16, N, K, hsm);
}

struct TriParams {
    const __half* W[3];
    const float*  b[3];
    __half*       C[3];
};

__global__ __launch_bounds__(256, 2)
void gemm_h_qkv(const __half* __restrict__ A, TriParams p, int N, int K)
{
    extern __shared__ __half hsm[];
    const int z = blockIdx.z;
    gemm_h_body<false, true>(A, p.W[z], p.b[z], (float*)0, p.C[z], N, K, hsm);
}

/* ------------------------------------------------------------------ */
/* fp16 tensor-core flash attention.                                   */
/* CTA 256 thr (8 warps), 128 q-rows; warp owns 16 rows.               */
/* KV tiles of 64 keys, double-buffered cp.async; P stays in regs.     */
/* SMEM halfs, stride 72: Qs[128][72], Ks[2][64][72], Vs[2][64][72].   */
/* ------------------------------------------------------------------ */
#define AT_STH 72
#define AT_Q_H   (128 * AT_STH)
#define AT_KV_H  (64 * AT_STH)
#define AT_SMEM_B ((AT_Q_H + 4 * AT_KV_H) * (int)sizeof(__half))  /* 55296 */

__global__ __launch_bounds__(256)
void attn_h_kernel(const __half* __restrict__ Q,
                   const __half* __restrict__ K,
                   const __half* __restrict__ V,
                   __half* __restrict__ O16)
{
    extern __shared__ __half asm_h[];
    __half* Qs = asm_h;                       /* [128][72] */
    __half* Ks = asm_h + AT_Q_H;              /* [2][64][72] */
    __half* Vs = asm_h + AT_Q_H + 2 * AT_KV_H;/* [2][64][72] */

    const int b  = blockIdx.z, h = blockIdx.y;
    const int q0 = blockIdx.x * 128;
    const int t = threadIdx.x, w = t >> 5, lane = t & 31;
    const int r = lane >> 2, c = lane & 3;
    const size_t base = ((size_t)b * SEQ) * D_MODEL + (size_t)h * D_HEAD;

    /* KV tile 0 -> buf 0: 64 rows x 8 segs of 8 halfs, 2 slots/thread */
#pragma unroll
    for (int i = 0; i < 2; i++) {
        int slot = t + i * 256;               /* 0..511 */
        int row = slot >> 3, sg = slot & 7;
        cpa16(&Ks[row * AT_STH + sg * 8], K + base + (size_t)row * D_MODEL + sg * 8);
        cpa16(&Vs[row * AT_STH + sg * 8], V + base + (size_t)row * D_MODEL + sg * 8);
    }
    CP_COMMIT();

    /* Q tile: 128 rows x 8 segs, 4 slots/thread (plain cp.async too) */
#pragma unroll
    for (int i = 0; i < 4; i++) {
        int slot = t + i * 256;               /* 0..1023 */
        int row = slot >> 3, sg = slot & 7;
        cpa16(&Qs[row * AT_STH + sg * 8],
              Q + base + (size_t)(q0 + row) * D_MODEL + sg * 8);
    }
    CP_COMMIT();
    CP_WAIT0();
    __syncthreads();

    /* hoist Q fragments: 4 k-chunks of 16 */
    uint32_t qf[4][4];
#pragma unroll
    for (int kt = 0; kt < 4; kt++) {
        const int kk = kt * 16;
        qf[kt][0] = *(const uint32_t*)&Qs[(w * 16 + r    ) * AT_STH + kk + 2*c    ];
        qf[kt][1] = *(const uint32_t*)&Qs[(w * 16 + r + 8) * AT_STH + kk + 2*c    ];
        qf[kt][2] = *(const uint32_t*)&Qs[(w * 16 + r    ) * AT_STH + kk + 2*c + 8];
        qf[kt][3] = *(const uint32_t*)&Qs[(w * 16 + r + 8) * AT_STH + kk + 2*c + 8];
    }

    float oacc[8][4];
#pragma unroll
    for (int nt = 0; nt < 8; nt++)
#pragma unroll
        for (int i = 0; i < 4; i++) oacc[nt][i] = 0.f;
    float m0 = -1e30f, m1 = -1e30f, l0 = 0.f, l1 = 0.f;
    const float scale = 0.125f;

    /* per-lane ldmatrix source offset (halfs) within a V k-chunk/ntile */
    const int lm_row = lane & 15;
    const int lm_col = (lane >> 4) * 8;

    const int ntiles = SEQ / 64;
    for (int it = 0; it < ntiles; ++it) {
        const int buf = it & 1;
        const bool has_next = (it + 1 < ntiles);
        __half* Kb = Ks + buf * AT_KV_H;
        __half* Vb = Vs + buf * AT_KV_H;

        if (has_next) {
            const int k0n = (it + 1) * 64;
            const int nb = buf ^ 1;
#pragma unroll
            for (int i = 0; i < 2; i++) {
                int slot = t + i * 256;
                int row = slot >> 3, sg = slot & 7;
                cpa16(&Ks[nb * AT_KV_H + row * AT_STH + sg * 8],
                      K + base + (size_t)(k0n + row) * D_MODEL + sg * 8);
                cpa16(&Vs[nb * AT_KV_H + row * AT_STH + sg * 8],
                      V + base + (size_t)(k0n + row) * D_MODEL + sg * 8);
            }
            CP_COMMIT();
            CP_WAIT1();
        } else {
            CP_WAIT0();
        }
        __syncthreads();

        /* ---- S = Q @ K^T : warp computes 16 x 64 ---- */
        float sacc[8][4];
#pragma unroll
        for (int nt = 0; nt < 8; nt++)
#pragma unroll
            for (int i = 0; i < 4; i++) sacc[nt][i] = 0.f;

#pragma unroll
        for (int kt = 0; kt < 4; kt++) {
            const int kk = kt * 16;
#pragma unroll
            for (int nt = 0; nt < 8; nt++) {
                uint32_t b0 = *(const uint32_t*)&Kb[(nt * 8 + r) * AT_STH + kk + 2*c    ];
                uint32_t b1 = *(const uint32_t*)&Kb[(nt * 8 + r) * AT_STH + kk + 2*c + 8];
                MMA_F16(sacc[nt], qf[kt], b0, b1);
            }
        }

        /* ---- online softmax, P packed to fp16 registers ---- */
        float mx0 = -1e30f, mx1 = -1e30f;
#pragma unroll
        for (int nt = 0; nt < 8; nt++) {
            mx0 = fmaxf(mx0, fmaxf(sacc[nt][0], sacc[nt][1]));
            mx1 = fmaxf(mx1, fmaxf(sacc[nt][2], sacc[nt][3]));
        }
        mx0 = fmaxf(mx0, __shfl_xor_sync(0xffffffffu, mx0, 1));
        mx0 = fmaxf(mx0, __shfl_xor_sync(0xffffffffu, mx0, 2));
        mx1 = fmaxf(mx1, __shfl_xor_sync(0xffffffffu, mx1, 1));
        mx1 = fmaxf(mx1, __shfl_xor_sync(0xffffffffu, mx1, 2));

        float mn0 = fmaxf(m0, mx0 * scale);
        float mn1 = fmaxf(m1, mx1 * scale);
        float a0 = __expf(m0 - mn0), a1 = __expf(m1 - mn1);
        m0 = mn0; m1 = mn1;

        uint32_t ph[8][2];
        float rs0 = 0.f, rs1 = 0.f;
#pragma unroll
        for (int nt = 0; nt < 8; nt++) {
            float p00 = __expf(sacc[nt][0] * scale - mn0);
            float p01 = __expf(sacc[nt][1] * scale - mn0);
            float p10 = __expf(sacc[nt][2] * scale - mn1);
            float p11 = __expf(sacc[nt][3] * scale - mn1);
            rs0 += p00 + p01; rs1 += p10 + p11;
            ph[nt][0] = packh2(p00, p01);     /* row r   */
            ph[nt][1] = packh2(p10, p11);     /* row r+8 */
        }
        rs0 += __shfl_xor_sync(0xffffffffu, rs0, 1);
        rs0 += __shfl_xor_sync(0xffffffffu, rs0, 2);
        rs1 += __shfl_xor_sync(0xffffffffu, rs1, 1);
        rs1 += __shfl_xor_sync(0xffffffffu, rs1, 2);
        l0 = l0 * a0 + rs0;
        l1 = l1 * a1 + rs1;
#pragma unroll
        for (int nt = 0; nt < 8; nt++) {
            oacc[nt][0] *= a0; oacc[nt][1] *= a0;
            oacc[nt][2] *= a1; oacc[nt][3] *= a1;
        }

        /* ---- O += P @ V : P from registers, V via ldmatrix.trans ---- */
#pragma unroll
        for (int kt = 0; kt < 4; kt++) {
            uint32_t af[4];
            af[0] = ph[2*kt    ][0];
            af[1] = ph[2*kt    ][1];
            af[2] = ph[2*kt + 1][0];
            af[3] = ph[2*kt + 1][1];
#pragma unroll
            for (int ntp = 0; ntp < 4; ntp++) {
                uint32_t v0, v1, v2, v3;
                uint32_t addr = (uint32_t)__cvta_generic_to_shared(
                    &Vb[(kt * 16 + lm_row) * AT_STH + ntp * 16 + lm_col]);
                LDSM_X4_TRANS(v0, v1, v2, v3, addr);
                MMA_F16(oacc[2*ntp    ], af, v0, v1);
                MMA_F16(oacc[2*ntp + 1], af, v2, v3);
            }
        }
        __syncthreads();   /* all reads of buf done before its re-fill */
    }

    /* ---- epilogue ---- */
    const float inv0 = 1.f / l0, inv1 = 1.f / l1;
    const int row0 = q0 + w * 16 + r;
#pragma unroll
    for (int nt = 0; nt < 8; nt++) {
        const int col = nt * 8 + 2 * c;
        *(__half2*)&O16[base + (size_t)row0 * D_MODEL + col] =
            __floats2half2_rn(oacc[nt][0] * inv0, oacc[nt][1] * inv0);
        *(__half2*)&O16[base + (size_t)(row0 + 8) * D_MODEL + col] =
            __floats2half2_rn(oacc[nt][2] * inv1, oacc[nt][3] * inv1);
    }
}

/* ------------------------------------------------------------------ */
/* Fused residual add + LayerNorm; optional fp16 mirror output         */
/* ------------------------------------------------------------------ */
__global__ __launch_bounds__(256)
void add_ln_kernel(const float* __restrict__ A,
                   const float* __restrict__ B,
                   const float* __restrict__ gamma,
                   const float* __restrict__ beta,
                   float* __restrict__ out,
                   __half* __restrict__ out16)
{
    const int row = blockIdx.x;
    const int t = threadIdx.x;
    const size_t roff = (size_t)row * D_MODEL;

    float4 va = *(const float4*)&A[roff + t * 4];
    float4 vb = *(const float4*)&B[roff + t * 4];
    float v0 = va.x + vb.x, v1 = va.y + vb.y, v2 = va.z + vb.z, v3 = va.w + vb.w;

    float s  = v0 + v1 + v2 + v3;
    float s2 = v0 * v0 + v1 * v1 + v2 * v2 + v3 * v3;

    __shared__ float red[2][8];
#pragma unroll
    for (int off = 16; off > 0; off >>= 1) {
        s  += __shfl_xor_sync(0xffffffffu, s,  off);
        s2 += __shfl_xor_sync(0xffffffffu, s2, off);
    }
    int warp = t >> 5, lane = t & 31;
    if (lane == 0) { red[0][warp] = s; red[1][warp] = s2; }
    __syncthreads();
    if (warp == 0) {
        s  = red[0][lane & 7];
        s2 = red[1][lane & 7];
#pragma unroll
        for (int off = 4; off > 0; off >>= 1) {
            s  += __shfl_xor_sync(0xffffffffu, s,  off);
            s2 += __shfl_xor_sync(0xffffffffu, s2, off);
        }
        if (lane == 0) { red[0][0] = s; red[1][0] = s2; }
    }
    __syncthreads();
    s  = red[0][0];
    s2 = red[1][0];

    const float inv_n = 1.f / (float)D_MODEL;
    float mu   = s * inv_n;
    float var  = s2 * inv_n - mu * mu;
    float rstd = rsqrtf(var + LN_EPS);

    float4 g4  = *(const float4*)&gamma[t * 4];
    float4 be4 = *(const float4*)&beta[t * 4];
    float4 o;
    o.x = (v0 - mu) * rstd * g4.x + be4.x;
    o.y = (v1 - mu) * rstd * g4.y + be4.y;
    o.z = (v2 - mu) * rstd * g4.z + be4.z;
    o.w = (v3 - mu) * rstd * g4.w + be4.w;
    *(float4*)&out[roff + t * 4] = o;
    if (out16) {
        *(__half2*)&out16[roff + t * 4]     = __floats2half2_rn(o.x, o.y);
        *(__half2*)&out16[roff + t * 4 + 2] = __floats2half2_rn(o.z, o.w);
    }
}

/* ------------------------------------------------------------------ */
/* Launcher                                                            */
/* ------------------------------------------------------------------ */
extern "C" void kernel_launch(void* const* d_in, const int* in_sizes, int n_in,
                              void* d_out, int out_size)
{
    const float* x   = (const float*)d_in[0];
    const float* Wq  = (const float*)d_in[1];
    const float* bq  = (const float*)d_in[2];
    const float* Wk  = (const float*)d_in[3];
    const float* bk  = (const float*)d_in[4];
    const float* Wv  = (const float*)d_in[5];
    const float* bv  = (const float*)d_in[6];
    const float* Wo  = (const float*)d_in[7];
    const float* bo  = (const float*)d_in[8];
    const float* W1  = (const float*)d_in[9];
    const float* b1  = (const float*)d_in[10];
    const float* W2  = (const float*)d_in[11];
    const float* b2  = (const float*)d_in[12];
    const float* g1  = (const float*)d_in[13];
    const float* be1 = (const float*)d_in[14];
    const float* g2  = (const float*)d_in[15];
    const float* be2 = (const float*)d_in[16];
    float* out = (float*)d_out;

    float *proj, *h, *f2;
    cudaGetSymbolAddress((void**)&proj, g_proj);
    cudaGetSymbolAddress((void**)&h,    g_h);
    cudaGetSymbolAddress((void**)&f2,   g_f2);

    __half *x16, *wq16, *wk16, *wv16, *wo16, *w116, *w216;
    __half *q16, *k16, *v16, *att16, *h16, *ffn16;
    cudaGetSymbolAddress((void**)&x16,   g_x16);
    cudaGetSymbolAddress((void**)&wq16,  g_wq16);
    cudaGetSymbolAddress((void**)&wk16,  g_wk16);
    cudaGetSymbolAddress((void**)&wv16,  g_wv16);
    cudaGetSymbolAddress((void**)&wo16,  g_wo16);
    cudaGetSymbolAddress((void**)&w116,  g_w116);
    cudaGetSymbolAddress((void**)&w216,  g_w216);
    cudaGetSymbolAddress((void**)&q16,   g_q16);
    cudaGetSymbolAddress((void**)&k16,   g_k16);
    cudaGetSymbolAddress((void**)&v16,   g_v16);
    cudaGetSymbolAddress((void**)&att16, g_att16);
    cudaGetSymbolAddress((void**)&h16,   g_h16);
    cudaGetSymbolAddress((void**)&ffn16, g_ffn16);

    static int attr_set = 0;
    if (!attr_set) {
        cudaFuncSetAttribute(attn_h_kernel,
                             cudaFuncAttributeMaxDynamicSharedMemorySize, AT_SMEM_B);
        cudaFuncSetAttribute(gemm_h<false, false>,
                             cudaFuncAttributeMaxDynamicSharedMemorySize, GEMM_SMEM_B);
        cudaFuncSetAttribute(gemm_h<true, true>,
                             cudaFuncAttributeMaxDynamicSharedMemorySize, GEMM_SMEM_B);
        cudaFuncSetAttribute(gemm_h_qkv,
                             cudaFuncAttributeMaxDynamicSharedMemorySize, GEMM_SMEM_B);
        attr_set = 1;
    }

    dim3 blk(256);

    /* convert inputs + weights to fp16 */
    f2h_kernel<<<(NTOK*D_MODEL)/1024, blk>>>(x,  x16,  NTOK*D_MODEL);
    f2h_kernel<<<(D_MODEL*D_MODEL)/1024, blk>>>(Wq, wq16, D_MODEL*D_MODEL);
    f2h_kernel<<<(D_MODEL*D_MODEL)/1024, blk>>>(Wk, wk16, D_MODEL*D_MODEL);
    f2h_kernel<<<(D_MODEL*D_MODEL)/1024, blk>>>(Wv, wv16, D_MODEL*D_MODEL);
    f2h_kernel<<<(D_MODEL*D_MODEL)/1024, blk>>>(Wo, wo16, D_MODEL*D_MODEL);
    f2h_kernel<<<(D_FF*D_MODEL)/1024, blk>>>(W1, w116, D_FF*D_MODEL);
    f2h_kernel<<<(D_MODEL*D_FF)/1024, blk>>>(W2, w216, D_MODEL*D_FF);

    /* merged QKV projections -> fp16 q,k,v */
    TriParams tp;
    tp.W[0] = wq16; tp.W[1] = wk16; tp.W[2] = wv16;
    tp.b[0] = bq;   tp.b[1] = bk;   tp.b[2] = bv;
    tp.C[0] = q16;  tp.C[1] = k16;  tp.C[2] = v16;
    dim3 g_qkv(D_MODEL / 128, NTOK / 128, 3);
    gemm_h_qkv<<<g_qkv, blk, GEMM_SMEM_B>>>(x16, tp, D_MODEL, D_MODEL);

    /* fp16 flash attention -> att16 */
    dim3 g_at(SEQ / 128, NHEAD, BATCH);
    attn_h_kernel<<<g_at, blk, AT_SMEM_B>>>(q16, k16, v16, att16);

    /* output projection (fp16 in, fp32 out) */
    dim3 g_sq(D_MODEL / 128, NTOK / 128);
    gemm_h<false, false><<<g_sq, blk, GEMM_SMEM_B>>>(att16, wo16, bo, proj,
                                                     (__half*)0, D_MODEL, D_MODEL);

    /* h = LN(x + proj), also h16 */
    add_ln_kernel<<<NTOK, blk>>>(x, proj, g1, be1, h, h16);

    /* FFN1 (ReLU, fp16 out) */
    dim3 g_f1(D_FF / 128, NTOK / 128);
    gemm_h<true, true><<<g_f1, blk, GEMM_SMEM_B>>>(h16, w116, b1, (float*)0,
                                                   ffn16, D_FF, D_MODEL);
    /* FFN2 (fp32 out) */
    gemm_h<false, false><<<g_sq, blk, GEMM_SMEM_B>>>(ffn16, w216, b2, f2,
                                                     (__half*)0, D_MODEL, D_FF);

    /* out = LN(h + f2) */
    add_ln_kernel<<<NTOK, blk>>>(h, f2, g2, be2, out, (__half*)0);
}